// round 11
// baseline (speedup 1.0000x reference)
#include <cuda_runtime.h>
#include <cuda_bf16.h>
#include <cstdint>

namespace gpf {
constexpr int Bn=128, Nn=4096, Pp=128, ROWS=261, TILE=64, NTILES=64, NT=1024;
constexpr float W0F=30.f, EPS=1e-5f;
constexpr int SQ=272;   // byte stride: w1 [k][o], q [n][p]
constexpr int SH=144;   // byte stride: h tiles [d][n]
constexpr int BY_W1H=0, BY_W1L=34816;
constexpr int BY_H1H=69632, BY_H1L=BY_H1H+18432, BY_H2H=BY_H1L+18432, BY_H2L=BY_H2H+18432;
constexpr int BY_Q1H=143360, BY_Q1L=BY_Q1H+17408, BY_Q2H=BY_Q1L+17408, BY_Q2L=BY_Q2H+17408;
constexpr int BY_W0=212992, BY_B0=BY_W0+1024, BY_B1=BY_B0+512, BY_W2=BY_B1+512,
  BY_B2=BY_W2+2048, BY_H3=BY_B2+32, BY_Z5=BY_H3+1024;
constexpr int SMEM_BYTES=BY_Z5+2560;  // 220704
}

#define LDSM4T(d,a) asm volatile( \
  "ldmatrix.sync.aligned.m8n8.x4.trans.shared.b16 {%0,%1,%2,%3},[%4];" \
  :"=r"((d)[0]),"=r"((d)[1]),"=r"((d)[2]),"=r"((d)[3]):"r"(a))
#define LDSM4(d,a) asm volatile( \
  "ldmatrix.sync.aligned.m8n8.x4.shared.b16 {%0,%1,%2,%3},[%4];" \
  :"=r"((d)[0]),"=r"((d)[1]),"=r"((d)[2]),"=r"((d)[3]):"r"(a))
#define MMAB(c,a,b0,b1) asm volatile( \
  "mma.sync.aligned.m16n8k16.row.col.f32.bf16.bf16.f32 " \
  "{%0,%1,%2,%3},{%4,%5,%6,%7},{%8,%9},{%0,%1,%2,%3};" \
  :"+f"((c)[0]),"+f"((c)[1]),"+f"((c)[2]),"+f"((c)[3]) \
  :"r"((a)[0]),"r"((a)[1]),"r"((a)[2]),"r"((a)[3]),"r"(b0),"r"(b1))

__device__ __forceinline__ uint32_t smem_u32(const void* p){
  uint32_t a; asm("{ .reg .u64 t; cvta.to.shared.u64 t, %1; cvt.u32.u64 %0, t; }":"=r"(a):"l"(p)); return a;
}
__device__ __forceinline__ uint32_t bfpair(float a, float b, uint32_t& lo){
  __nv_bfloat16 ha=__float2bfloat16(a), hb=__float2bfloat16(b);
  __nv_bfloat162 l; l.x=__float2bfloat16(a-__bfloat162float(ha)); l.y=__float2bfloat16(b-__bfloat162float(hb));
  lo=*(uint32_t*)&l;
  __nv_bfloat162 h; h.x=ha; h.y=hb; return *(uint32_t*)&h;
}
__device__ __forceinline__ void ln_row_write(float4 v, const float* g, const float* bb,
                                             float* orow, int lane){
  float s=(v.x+v.y)+(v.z+v.w);
  #pragma unroll
  for(int o=16;o>0;o>>=1) s+=__shfl_xor_sync(0xffffffffu,s,o);
  float m=s*(1.f/128.f);
  float cx=v.x-m, cy=v.y-m, cz=v.z-m, cw=v.w-m;
  float q=(cx*cx+cy*cy)+(cz*cz+cw*cw);
  #pragma unroll
  for(int o=16;o>0;o>>=1) q+=__shfl_xor_sync(0xffffffffu,q,o);
  float inv=rsqrtf(q*(1.f/128.f)+gpf::EPS);
  float4 gv=*(const float4*)(g+lane*4), bv=*(const float4*)(bb+lane*4);
  float4 ov={cx*inv*gv.x+bv.x, cy*inv*gv.y+bv.y, cz*inv*gv.z+bv.z, cw*inv*gv.w+bv.w};
  *(float4*)(orow+lane*4)=ov;
}

// 3-pass bf16 MMA, A TRANS from [k][m] stride SA; B TRANS from [k][j] stride SB.
template<int KS, int NB8>
__device__ __forceinline__ void gemm3_t(float (*c)[4], uint32_t AH, uint32_t AL,
    uint32_t BH, uint32_t BL, int lane, int m0, int j0, int SA, int SB){
  const int r=lane&7, g=lane>>3;
  const uint32_t ao=(uint32_t)(((g&2)*4+r)*SA + (m0+(g&1)*8)*2);
  const uint32_t bo=(uint32_t)(((g&1)*8+r)*SB + (g>>1)*16 + j0*2);
  #pragma unroll
  for(int kk=0;kk<KS;++kk){
    uint32_t ah[4], al[4];
    LDSM4T(ah, AH+kk*16*SA+ao); LDSM4T(al, AL+kk*16*SA+ao);
    #pragma unroll
    for(int b2=0;b2<NB8/2;++b2){
      uint32_t bh[4], bl[4], cb=(uint32_t)(kk*16*SB)+bo+b2*32;
      LDSM4T(bh, BH+cb); LDSM4T(bl, BL+cb);
      MMAB(c[2*b2],ah,bh[0],bh[1]); MMAB(c[2*b2],ah,bl[0],bl[1]); MMAB(c[2*b2],al,bh[0],bh[1]);
      MMAB(c[2*b2+1],ah,bh[2],bh[3]); MMAB(c[2*b2+1],ah,bl[2],bl[3]); MMAB(c[2*b2+1],al,bh[2],bh[3]);
    }
  }
}
// 3-pass bf16 MMA, A NON-TRANS from [m][k] stride SA; B TRANS from [k][j] stride SB.
template<int KS, int NB8>
__device__ __forceinline__ void gemm3_nt(float (*c)[4], uint32_t AH, uint32_t AL,
    uint32_t BH, uint32_t BL, int lane, int m0, int j0, int SA, int SB){
  const int r=lane&7, g=lane>>3;
  const uint32_t ao=(uint32_t)((m0+(g&1)*8+r)*SA + (g&2)*8);
  const uint32_t bo=(uint32_t)(((g&1)*8+r)*SB + (g>>1)*16 + j0*2);
  #pragma unroll
  for(int kk=0;kk<KS;++kk){
    uint32_t ah[4], al[4];
    LDSM4(ah, AH+kk*32+ao); LDSM4(al, AL+kk*32+ao);
    #pragma unroll
    for(int b2=0;b2<NB8/2;++b2){
      uint32_t bh[4], bl[4], cb=(uint32_t)(kk*16*SB)+bo+b2*32;
      LDSM4T(bh, BH+cb); LDSM4T(bl, BL+cb);
      MMAB(c[2*b2],ah,bh[0],bh[1]); MMAB(c[2*b2],ah,bl[0],bl[1]); MMAB(c[2*b2],al,bh[0],bh[1]);
      MMAB(c[2*b2+1],ah,bh[2],bh[3]); MMAB(c[2*b2+1],ah,bl[2],bl[3]); MMAB(c[2*b2+1],al,bh[2],bh[3]);
    }
  }
}

__global__ __launch_bounds__(gpf::NT,1)
void gpf_kernel(const float* __restrict__ w0g, const float* __restrict__ w1g,
                const float* __restrict__ w2g, const float* __restrict__ b0g,
                const float* __restrict__ b1g, const float* __restrict__ b2g,
                const float* __restrict__ xg,  const float* __restrict__ pwg,
                const float* __restrict__ pbg, const float* __restrict__ lngg,
                const float* __restrict__ lnbg, float* __restrict__ outg){
  using namespace gpf;
  extern __shared__ char smc[];
  const int b=blockIdx.x, t=threadIdx.x, lane=t&31, wid=t>>5;   // wid 0..31
  char *w1h=smc+BY_W1H, *w1l=smc+BY_W1L;
  char *h1h=smc+BY_H1H, *h1l=smc+BY_H1L, *h2h=smc+BY_H2H, *h2l=smc+BY_H2L;
  char *q1h=smc+BY_Q1H, *q1l=smc+BY_Q1L, *q2h=smc+BY_Q2H, *q2l=smc+BY_Q2L;
  float* w0s=(float*)(smc+BY_W0); float* b0s=(float*)(smc+BY_B0); float* b1s=(float*)(smc+BY_B1);
  float* w2s=(float*)(smc+BY_W2); float* b2s=(float*)(smc+BY_B2);
  float* h3s=(float*)(smc+BY_H3); float* z5s=(float*)(smc+BY_Z5);
  const uint32_t W1H=smem_u32(w1h), W1L=smem_u32(w1l);
  const uint32_t H1H=smem_u32(h1h), H1L=smem_u32(h1l), H2H=smem_u32(h2h), H2L=smem_u32(h2l);
  const uint32_t Q1H=smem_u32(q1h), Q1L=smem_u32(q1l), Q2H=smem_u32(q2h), Q2L=smem_u32(q2l);

  { // one-time: w1 -> bf16 hi/lo [k][o]; params
    int po=t&63, k0=t>>6;   // k0 0..15
    #pragma unroll
    for(int it=0;it<8;++it){
      int k=k0+it*16;
      float2 v=*(const float2*)(w1g+(size_t)b*16384+k*128+2*po);
      uint32_t lo, hi=bfpair(v.x,v.y,lo);
      *(uint32_t*)(w1h+k*SQ+po*4)=hi; *(uint32_t*)(w1l+k*SQ+po*4)=lo;
    }
    if(t<256) w0s[t]=w0g[b*256+t];
    else if(t<384) b0s[t-256]=b0g[b*128+(t-256)];
    else if(t<512) b1s[t-384]=b1g[b*128+(t-384)];
    if(t<128){
      w2s[t*4+0]=w2g[b*384+t*3+0]; w2s[t*4+1]=w2g[b*384+t*3+1]; w2s[t*4+2]=w2g[b*384+t*3+2];
    }
    if(t>=512&&t<515) b2s[t-512]=b2g[b*3+(t-512)];
  }

  float c1[4][4], c2[4][4];
  #pragma unroll
  for(int i=0;i<4;++i){ c1[i][0]=c1[i][1]=c1[i][2]=c1[i][3]=0.f; c2[i][0]=c2[i][1]=c2[i][2]=c2[i][3]=0.f; }
  float z3acc=0.f, z0a0=0.f, z0a1=0.f;
  const int d0w=(wid&7)*16, pB=(wid>>3)*32;   // C/D: 16d x 32p per warp
  const int oB=(wid&7)*16, nC=(wid>>3)*16;    // B:   16o x 16n per warp
  const int p2=t&63, nq0=t>>6;                // nq0 0..15

  for(int tile=0; tile<NTILES; ++tile){
    const int n0=tile*TILE;
    __syncthreads();

    { // Phase A: h1=sin(30*(x@w0+b0)) -> [d][n] bf16 hi/lo; convert pw1,pw2 -> [n][p]
      float4 xv=*(const float4*)(xg+(size_t)n0*2+lane*4);
      #pragma unroll
      for(int it=0;it<4;++it){
        int d=wid+it*32;
        float wa=w0s[d], wb=w0s[128+d], bi=b0s[d];
        float s0=__sinf(W0F*fmaf(xv.x,wa,fmaf(xv.y,wb,bi)));
        float s1=__sinf(W0F*fmaf(xv.z,wa,fmaf(xv.w,wb,bi)));
        uint32_t lo, hi=bfpair(s0,s1,lo);
        *(uint32_t*)(h1h+d*SH+lane*4)=hi; *(uint32_t*)(h1l+d*SH+lane*4)=lo;
      }
      #pragma unroll
      for(int it=0;it<4;++it){
        int n2=nq0+it*16;
        float2 v1=*(const float2*)(pwg+(size_t)1*Nn*Pp+(size_t)(n0+n2)*Pp+2*p2);
        float2 v2=*(const float2*)(pwg+(size_t)2*Nn*Pp+(size_t)(n0+n2)*Pp+2*p2);
        uint32_t lo1, hi1=bfpair(v1.x,v1.y,lo1);
        uint32_t lo2, hi2=bfpair(v2.x,v2.y,lo2);
        *(uint32_t*)(q1h+n2*SQ+p2*4)=hi1; *(uint32_t*)(q1l+n2*SQ+p2*4)=lo1;
        *(uint32_t*)(q2h+n2*SQ+p2*4)=hi2; *(uint32_t*)(q2l+n2*SQ+p2*4)=lo2;
      }
    }
    __syncthreads();

    { // Phase B (HMMA): h2^T[o][n] = sin(30*(w1^T h1 + b1)); 16o x 16n per warp
      float c[2][4];
      c[0][0]=c[0][1]=c[0][2]=c[0][3]=0.f; c[1][0]=c[1][1]=c[1][2]=c[1][3]=0.f;
      gemm3_t<8,2>(c, W1H,W1L, H1H,H1L, lane, oB, nC, SQ, SH);
      int o0=oB+(lane>>2);
      float bia0=b1s[o0], bia1=b1s[o0+8];
      #pragma unroll
      for(int bb=0;bb<2;++bb){
        int n=nC+bb*8+2*(lane&3);
        float s0=__sinf(W0F*(c[bb][0]+bia0)), s1=__sinf(W0F*(c[bb][1]+bia0));
        float s2=__sinf(W0F*(c[bb][2]+bia1)), s3=__sinf(W0F*(c[bb][3]+bia1));
        uint32_t lo0, hi0=bfpair(s0,s1,lo0);
        uint32_t lo1, hi1=bfpair(s2,s3,lo1);
        *(uint32_t*)(h2h+o0*SH+n*2)=hi0;     *(uint32_t*)(h2l+o0*SH+n*2)=lo0;
        *(uint32_t*)(h2h+(o0+8)*SH+n*2)=hi1; *(uint32_t*)(h2l+(o0+8)*SH+n*2)=lo1;
      }
    }
    // Phase C: z1 += h1^T @ pw1
    gemm3_nt<4,4>(c1, H1H,H1L, Q1H,Q1L, lane, d0w, pB, SH, SQ);
    __syncthreads();

    // Phase E (threads 320-511): h3[n][j] from h2^T
    if(t>=320&&t<512){
      int u=t-320, n=u/3, j=u-n*3;
      float acc=b2s[j];
      #pragma unroll 8
      for(int o=0;o<128;++o){
        float hv=__bfloat162float(*(__nv_bfloat16*)(h2h+o*SH+n*2));
        float lv=__bfloat162float(*(__nv_bfloat16*)(h2l+o*SH+n*2));
        acc=fmaf(hv+lv, w2s[o*4+j], acc);
      }
      h3s[n*4+j]=acc;
    }
    // Phase D: z2 += h2^T @ pw2
    gemm3_nt<4,4>(c2, H2H,H2L, Q2H,Q2L, lane, d0w, pB, SH, SQ);
    __syncthreads();

    if(t<384){ // z3 += h3^T @ pw3
      int j=t>>7, p=t&127;
      const float* pw3=pwg+(size_t)3*Nn*Pp+(size_t)n0*Pp+p;
      float ta=0.f, tb=0.f;
      #pragma unroll 8
      for(int n=0;n<TILE;n+=2){
        ta=fmaf(h3s[n*4+j],     pw3[n*Pp],     ta);
        tb=fmaf(h3s[(n+1)*4+j], pw3[(n+1)*Pp], tb);
      }
      z3acc+=ta+tb;
    } else if(t<512){ // z0 partial
      int p=t-384;
      const float* pw0=pwg+(size_t)n0*Pp+p;
      const float* xp=xg+n0*2;
      float a0=0.f, a1=0.f;
      #pragma unroll 8
      for(int n=0;n<TILE;++n){ float w=pw0[n*Pp]; a0=fmaf(xp[n*2],w,a0); a1=fmaf(xp[n*2+1],w,a1); }
      z0a0+=a0; z0a1+=a1;
    }
  }

  // ===== epilogue =====
  __syncthreads();
  float* zs=(float*)(smc+BY_H1H);  // h tiles dead: staging
  const int rb=d0w+(lane>>2), cb0=pB+2*(lane&3);
  {
    const float* pb1=pbg+128;
    #pragma unroll
    for(int bb=0;bb<4;++bb){
      int col=cb0+bb*8;
      zs[rb*128+col]      =c1[bb][0]+pb1[col];
      zs[rb*128+col+1]    =c1[bb][1]+pb1[col+1];
      zs[(rb+8)*128+col]  =c1[bb][2]+pb1[col];
      zs[(rb+8)*128+col+1]=c1[bb][3]+pb1[col+1];
    }
  }
  __syncthreads();
  {
    const float* g=lngg+128; const float* bb=lnbg+128;
    #pragma unroll
    for(int r=0;r<4;++r){
      int row=wid*4+r;
      float4 v=*(const float4*)(zs+row*128+lane*4);
      ln_row_write(v,g,bb,outg+((size_t)b*ROWS+2+row)*Pp,lane);
    }
  }
  __syncthreads();
  {
    const float* pb2=pbg+256;
    #pragma unroll
    for(int bb=0;bb<4;++bb){
      int col=cb0+bb*8;
      zs[rb*128+col]      =c2[bb][0]+pb2[col];
      zs[rb*128+col+1]    =c2[bb][1]+pb2[col+1];
      zs[(rb+8)*128+col]  =c2[bb][2]+pb2[col];
      zs[(rb+8)*128+col+1]=c2[bb][3]+pb2[col+1];
    }
  }
  __syncthreads();
  {
    const float* g=lngg+256; const float* bb=lnbg+256;
    #pragma unroll
    for(int r=0;r<4;++r){
      int row=wid*4+r;
      float4 v=*(const float4*)(zs+row*128+lane*4);
      ln_row_write(v,g,bb,outg+((size_t)b*ROWS+130+row)*Pp,lane);
    }
  }
  if(t>=384&&t<512){
    int p=t-384;
    z5s[p]=z0a0+pbg[p]; z5s[Pp+p]=z0a1+pbg[p];
  }
  if(t<384){
    int j=t>>7, p=t&127;
    z5s[(2+j)*Pp+p]=z3acc+pbg[3*128+p];
  }
  __syncthreads();
  if(wid<5){
    int row=wid, feat=(row<2)?0:3, outrow=(row<2)?row:(256+row);
    float4 v=*(const float4*)(z5s+row*Pp+lane*4);
    ln_row_write(v, lngg+feat*128, lnbg+feat*128,
                 outg+((size_t)b*ROWS+outrow)*Pp, lane);
  }
}

extern "C" void kernel_launch(void* const* d_in, const int* in_sizes, int n_in,
                              void* d_out, int out_size){
  (void)in_sizes;(void)n_in;(void)out_size;
  cudaFuncSetAttribute(gpf_kernel, cudaFuncAttributeMaxDynamicSharedMemorySize, gpf::SMEM_BYTES);
  gpf_kernel<<<gpf::Bn, gpf::NT, gpf::SMEM_BYTES>>>(
    (const float*)d_in[0],(const float*)d_in[1],(const float*)d_in[2],(const float*)d_in[3],
    (const float*)d_in[4],(const float*)d_in[5],(const float*)d_in[6],(const float*)d_in[7],
    (const float*)d_in[8],(const float*)d_in[9],(const float*)d_in[10],(float*)d_out);
}

// round 12
// speedup vs baseline: 1.0971x; 1.0971x over previous
#include <cuda_runtime.h>
#include <cuda_bf16.h>
#include <cstdint>

namespace gpf {
constexpr int Bn=128, Nn=4096, Pp=128, ROWS=261, TILE=64, NTILES=64, NT=512;
constexpr float W0F=30.f, EPS=1e-5f;
constexpr int SQ=272;   // byte stride: w1 [k][o], q [n][p]
constexpr int SH=144;   // byte stride: h tiles [d][n]
constexpr int BY_W1H=0, BY_W1L=34816;
constexpr int BY_H1H=69632, BY_H1L=BY_H1H+18432, BY_H2H=BY_H1L+18432, BY_H2L=BY_H2H+18432;
constexpr int BY_Q1H=143360, BY_Q1L=BY_Q1H+17408, BY_Q2H=BY_Q1L+17408, BY_Q2L=BY_Q2H+17408;
constexpr int BY_W0=212992, BY_B0=BY_W0+1024, BY_B1=BY_B0+512, BY_W2=BY_B1+512,
  BY_B2=BY_W2+2048, BY_H3=BY_B2+32, BY_Z5=BY_H3+2048;
constexpr int SMEM_BYTES=BY_Z5+2560;  // 221728
}

#define LDSM4T(d,a) asm volatile( \
  "ldmatrix.sync.aligned.m8n8.x4.trans.shared.b16 {%0,%1,%2,%3},[%4];" \
  :"=r"((d)[0]),"=r"((d)[1]),"=r"((d)[2]),"=r"((d)[3]):"r"(a))
#define LDSM4(d,a) asm volatile( \
  "ldmatrix.sync.aligned.m8n8.x4.shared.b16 {%0,%1,%2,%3},[%4];" \
  :"=r"((d)[0]),"=r"((d)[1]),"=r"((d)[2]),"=r"((d)[3]):"r"(a))
#define MMAB(c,a,b0,b1) asm volatile( \
  "mma.sync.aligned.m16n8k16.row.col.f32.bf16.bf16.f32 " \
  "{%0,%1,%2,%3},{%4,%5,%6,%7},{%8,%9},{%0,%1,%2,%3};" \
  :"+f"((c)[0]),"+f"((c)[1]),"+f"((c)[2]),"+f"((c)[3]) \
  :"r"((a)[0]),"r"((a)[1]),"r"((a)[2]),"r"((a)[3]),"r"(b0),"r"(b1))

__device__ __forceinline__ uint32_t smem_u32(const void* p){
  uint32_t a; asm("{ .reg .u64 t; cvta.to.shared.u64 t, %1; cvt.u32.u64 %0, t; }":"=r"(a):"l"(p)); return a;
}
__device__ __forceinline__ uint32_t bfpair(float a, float b, uint32_t& lo){
  __nv_bfloat16 ha=__float2bfloat16(a), hb=__float2bfloat16(b);
  __nv_bfloat162 l; l.x=__float2bfloat16(a-__bfloat162float(ha)); l.y=__float2bfloat16(b-__bfloat162float(hb));
  lo=*(uint32_t*)&l;
  __nv_bfloat162 h; h.x=ha; h.y=hb; return *(uint32_t*)&h;
}
__device__ __forceinline__ void ln_row_write(float4 v, const float* g, const float* bb,
                                             float* orow, int lane){
  float s=(v.x+v.y)+(v.z+v.w);
  #pragma unroll
  for(int o=16;o>0;o>>=1) s+=__shfl_xor_sync(0xffffffffu,s,o);
  float m=s*(1.f/128.f);
  float cx=v.x-m, cy=v.y-m, cz=v.z-m, cw=v.w-m;
  float q=(cx*cx+cy*cy)+(cz*cz+cw*cw);
  #pragma unroll
  for(int o=16;o>0;o>>=1) q+=__shfl_xor_sync(0xffffffffu,q,o);
  float inv=rsqrtf(q*(1.f/128.f)+gpf::EPS);
  float4 gv=*(const float4*)(g+lane*4), bv=*(const float4*)(bb+lane*4);
  float4 ov={cx*inv*gv.x+bv.x, cy*inv*gv.y+bv.y, cz*inv*gv.z+bv.z, cw*inv*gv.w+bv.w};
  *(float4*)(orow+lane*4)=ov;
}

// 3-pass bf16 MMA, A TRANS from [k][m] stride SA; B TRANS from [k][j] stride SB.
template<int KS, int NB8>
__device__ __forceinline__ void gemm3_t(float (*c)[4], uint32_t AH, uint32_t AL,
    uint32_t BH, uint32_t BL, int lane, int m0, int j0, int SA, int SB){
  const int r=lane&7, g=lane>>3;
  const uint32_t ao=(uint32_t)(((g&2)*4+r)*SA + (m0+(g&1)*8)*2);
  const uint32_t bo=(uint32_t)(((g&1)*8+r)*SB + (g>>1)*16 + j0*2);
  #pragma unroll
  for(int kk=0;kk<KS;++kk){
    uint32_t ah[4], al[4];
    LDSM4T(ah, AH+kk*16*SA+ao); LDSM4T(al, AL+kk*16*SA+ao);
    #pragma unroll
    for(int b2=0;b2<NB8/2;++b2){
      uint32_t bh[4], bl[4], cb=(uint32_t)(kk*16*SB)+bo+b2*32;
      LDSM4T(bh, BH+cb); LDSM4T(bl, BL+cb);
      MMAB(c[2*b2],ah,bh[0],bh[1]); MMAB(c[2*b2],ah,bl[0],bl[1]); MMAB(c[2*b2],al,bh[0],bh[1]);
      MMAB(c[2*b2+1],ah,bh[2],bh[3]); MMAB(c[2*b2+1],ah,bl[2],bl[3]); MMAB(c[2*b2+1],al,bh[2],bh[3]);
    }
  }
}
// 3-pass bf16 MMA, A NON-TRANS from [m][k] stride SA; B TRANS from [k][j] stride SB.
template<int KS, int NB8>
__device__ __forceinline__ void gemm3_nt(float (*c)[4], uint32_t AH, uint32_t AL,
    uint32_t BH, uint32_t BL, int lane, int m0, int j0, int SA, int SB){
  const int r=lane&7, g=lane>>3;
  const uint32_t ao=(uint32_t)((m0+(g&1)*8+r)*SA + (g&2)*8);
  const uint32_t bo=(uint32_t)(((g&1)*8+r)*SB + (g>>1)*16 + j0*2);
  #pragma unroll
  for(int kk=0;kk<KS;++kk){
    uint32_t ah[4], al[4];
    LDSM4(ah, AH+kk*32+ao); LDSM4(al, AL+kk*32+ao);
    #pragma unroll
    for(int b2=0;b2<NB8/2;++b2){
      uint32_t bh[4], bl[4], cb=(uint32_t)(kk*16*SB)+bo+b2*32;
      LDSM4T(bh, BH+cb); LDSM4T(bl, BL+cb);
      MMAB(c[2*b2],ah,bh[0],bh[1]); MMAB(c[2*b2],ah,bl[0],bl[1]); MMAB(c[2*b2],al,bh[0],bh[1]);
      MMAB(c[2*b2+1],ah,bh[2],bh[3]); MMAB(c[2*b2+1],ah,bl[2],bl[3]); MMAB(c[2*b2+1],al,bh[2],bh[3]);
    }
  }
}

// ---- pre-kernel: pw1/pw2 -> bf16 hi/lo device globals (once per launch) ----
__device__ __nv_bfloat16 g_pwh[2u*4096u*128u];
__device__ __nv_bfloat16 g_pwl[2u*4096u*128u];
__global__ void cvt_pw_kernel(const float* __restrict__ pwg){
  unsigned i=blockIdx.x*blockDim.x+threadIdx.x;           // 262144 threads, 4 floats each
  float4 v=((const float4*)(pwg+524288))[i];              // feats 1,2 contiguous
  uint32_t l0,h0,l1,h1;
  h0=bfpair(v.x,v.y,l0); h1=bfpair(v.z,v.w,l1);
  ((uint2*)g_pwh)[i]=make_uint2(h0,h1);
  ((uint2*)g_pwl)[i]=make_uint2(l0,l1);
}

__global__ __launch_bounds__(gpf::NT,1)
void gpf_kernel(const float* __restrict__ w0g, const float* __restrict__ w1g,
                const float* __restrict__ w2g, const float* __restrict__ b0g,
                const float* __restrict__ b1g, const float* __restrict__ b2g,
                const float* __restrict__ xg,  const float* __restrict__ pwg,
                const float* __restrict__ pbg, const float* __restrict__ lngg,
                const float* __restrict__ lnbg, float* __restrict__ outg){
  using namespace gpf;
  extern __shared__ char smc[];
  const int b=blockIdx.x, t=threadIdx.x, lane=t&31, wid=t>>5;
  char *w1h=smc+BY_W1H, *w1l=smc+BY_W1L;
  char *h1h=smc+BY_H1H, *h1l=smc+BY_H1L, *h2h=smc+BY_H2H, *h2l=smc+BY_H2L;
  char *q1h=smc+BY_Q1H, *q1l=smc+BY_Q1L, *q2h=smc+BY_Q2H, *q2l=smc+BY_Q2L;
  float* w0s=(float*)(smc+BY_W0); float* b0s=(float*)(smc+BY_B0); float* b1s=(float*)(smc+BY_B1);
  float* w2s=(float*)(smc+BY_W2); float* b2s=(float*)(smc+BY_B2);
  float* h3s=(float*)(smc+BY_H3); float* z5s=(float*)(smc+BY_Z5);
  const uint32_t W1H=smem_u32(w1h), W1L=smem_u32(w1l);
  const uint32_t H1H=smem_u32(h1h), H1L=smem_u32(h1l), H2H=smem_u32(h2h), H2L=smem_u32(h2l);
  const uint32_t Q1H=smem_u32(q1h), Q1L=smem_u32(q1l), Q2H=smem_u32(q2h), Q2L=smem_u32(q2l);

  { // one-time: w1 -> bf16 hi/lo [k][o]; params
    int po=t&63, k0=t>>6;
    #pragma unroll
    for(int it=0;it<16;++it){
      int k=k0+it*8;
      float2 v=*(const float2*)(w1g+(size_t)b*16384+k*128+2*po);
      uint32_t lo, hi=bfpair(v.x,v.y,lo);
      *(uint32_t*)(w1h+k*SQ+po*4)=hi; *(uint32_t*)(w1l+k*SQ+po*4)=lo;
    }
    if(t<256) w0s[t]=w0g[b*256+t];
    else if(t<384) b0s[t-256]=b0g[b*128+(t-256)];
    else b1s[t-384]=b1g[b*128+(t-384)];
    if(t<128){
      w2s[t*4+0]=w2g[b*384+t*3+0]; w2s[t*4+1]=w2g[b*384+t*3+1]; w2s[t*4+2]=w2g[b*384+t*3+2];
    }
    if(t<3) b2s[t]=b2g[b*3+t];
  }

  float c1[8][4], c2[8][4];
  #pragma unroll
  for(int i=0;i<8;++i){ c1[i][0]=c1[i][1]=c1[i][2]=c1[i][3]=0.f; c2[i][0]=c2[i][1]=c2[i][2]=c2[i][3]=0.f; }
  float z3acc=0.f, z0a0=0.f, z0a1=0.f;
  const int d0w=(wid&7)*16, pB=(wid>>3)*64;   // C/D: 16d x 64p per warp
  const int oB=(wid&7)*16, nC=(wid>>3)*32;    // B:   16o x 32n per warp
  const int npf=t>>3, seg=t&7;                // q-copy mapping (64 rows x 8 segs of 32B)
  const uint4* GH=(const uint4*)g_pwh;
  const uint4* GL=(const uint4*)g_pwl;
  uint4 pf[8];
  #define DO_PREFETCH(N0) do{ \
    size_t i1=(size_t)((N0)+npf)*16 + seg*2; \
    pf[0]=GH[i1]; pf[1]=GH[i1+1]; pf[2]=GL[i1]; pf[3]=GL[i1+1]; \
    pf[4]=GH[i1+65536]; pf[5]=GH[i1+65537]; pf[6]=GL[i1+65536]; pf[7]=GL[i1+65537]; \
  }while(0)
  DO_PREFETCH(0);

  for(int tile=0; tile<NTILES; ++tile){
    const int n0=tile*TILE;
    __syncthreads();

    { // Phase A: store prefetched q tiles; h1=sin(30*(x@w0+b0)) -> [d][n] bf16 hi/lo
      { char* d=q1h+npf*SQ+seg*32; *(uint4*)d=pf[0]; *(uint4*)(d+16)=pf[1]; }
      { char* d=q1l+npf*SQ+seg*32; *(uint4*)d=pf[2]; *(uint4*)(d+16)=pf[3]; }
      { char* d=q2h+npf*SQ+seg*32; *(uint4*)d=pf[4]; *(uint4*)(d+16)=pf[5]; }
      { char* d=q2l+npf*SQ+seg*32; *(uint4*)d=pf[6]; *(uint4*)(d+16)=pf[7]; }
      float4 xv=*(const float4*)(xg+(size_t)n0*2+lane*4);
      #pragma unroll
      for(int it=0;it<8;++it){
        int d=wid+it*16;
        float wa=w0s[d], wb=w0s[128+d], bi=b0s[d];
        float s0=__sinf(W0F*fmaf(xv.x,wa,fmaf(xv.y,wb,bi)));
        float s1=__sinf(W0F*fmaf(xv.z,wa,fmaf(xv.w,wb,bi)));
        uint32_t lo, hi=bfpair(s0,s1,lo);
        *(uint32_t*)(h1h+d*SH+lane*4)=hi; *(uint32_t*)(h1l+d*SH+lane*4)=lo;
      }
    }
    __syncthreads();

    { // Phase B (HMMA): h2^T[o][n] = sin(30*(w1^T h1 + b1))
      float c[4][4];
      #pragma unroll
      for(int i=0;i<4;++i){ c[i][0]=c[i][1]=c[i][2]=c[i][3]=0.f; }
      gemm3_t<8,4>(c, W1H,W1L, H1H,H1L, lane, oB, nC, SQ, SH);
      int o0=oB+(lane>>2);
      float bia0=b1s[o0], bia1=b1s[o0+8];
      #pragma unroll
      for(int bb=0;bb<4;++bb){
        int n=nC+(bb>>1)*16+(bb&1)*8+2*(lane&3);
        float s0=__sinf(W0F*(c[bb][0]+bia0)), s1=__sinf(W0F*(c[bb][1]+bia0));
        float s2=__sinf(W0F*(c[bb][2]+bia1)), s3=__sinf(W0F*(c[bb][3]+bia1));
        uint32_t lo0, hi0=bfpair(s0,s1,lo0);
        uint32_t lo1, hi1=bfpair(s2,s3,lo1);
        *(uint32_t*)(h2h+o0*SH+n*2)=hi0;     *(uint32_t*)(h2l+o0*SH+n*2)=lo0;
        *(uint32_t*)(h2h+(o0+8)*SH+n*2)=hi1; *(uint32_t*)(h2l+(o0+8)*SH+n*2)=lo1;
      }
    }
    // Phase C: z1 += h1^T @ pw1
    gemm3_nt<4,8>(c1, H1H,H1L, Q1H,Q1L, lane, d0w, pB, SH, SQ);
    __syncthreads();

    // Phase D: z2 += h2^T @ pw2 (MMAs first so the tensor pipe is fed early)
    gemm3_nt<4,8>(c2, H2H,H2L, Q2H,Q2L, lane, d0w, pB, SH, SQ);

    if(t<128){ // z0 partial on warps 0-3 (independent of smem phases)
      int p=t;
      const float* pw0=pwg+(size_t)n0*Pp+p;
      const float* xp=xg+n0*2;
      float a0=0.f, a1=0.f;
      #pragma unroll 8
      for(int n=0;n<TILE;++n){ float w=pw0[n*Pp]; a0=fmaf(xp[n*2],w,a0); a1=fmaf(xp[n*2+1],w,a1); }
      z0a0+=a0; z0a1+=a1;
    } else { // Phase E on 384 threads: h3 partials, 2-way o-split
      int u=t-128, half=u>=192, v=u-half*192, n=v/3, j=v-n*3;
      float acc = half? 0.f : b2s[j];
      const char* ph=h2h+(half*64)*SH+n*2;
      const char* pl=h2l+(half*64)*SH+n*2;
      const float* wj=w2s+(half*64)*4+j;
      #pragma unroll 8
      for(int o=0;o<64;++o){
        float hv=__bfloat162float(*(const __nv_bfloat16*)(ph+o*SH));
        float lv=__bfloat162float(*(const __nv_bfloat16*)(pl+o*SH));
        acc=fmaf(hv+lv, wj[o*4], acc);
      }
      h3s[half*256+n*4+j]=acc;
    }
    __syncthreads();

    // Phase F: z3 on warps 0-11; prefetch next q tiles (all threads)
    DO_PREFETCH((tile+1<NTILES)?(tile+1)*TILE:0);
    if(t<384){
      int j=t>>7, p=t&127;
      const float* pw3=pwg+(size_t)3*Nn*Pp+(size_t)n0*Pp+p;
      float ta=0.f, tb=0.f;
      #pragma unroll 8
      for(int n=0;n<TILE;n+=2){
        float h3a=h3s[n*4+j]+h3s[256+n*4+j];
        float h3b=h3s[(n+1)*4+j]+h3s[256+(n+1)*4+j];
        ta=fmaf(h3a, pw3[n*Pp],     ta);
        tb=fmaf(h3b, pw3[(n+1)*Pp], tb);
      }
      z3acc+=ta+tb;
    }
  }

  // ===== epilogue =====
  __syncthreads();
  float* zs=(float*)(smc+BY_H1H);  // h tiles dead: staging
  const int rb=d0w+(lane>>2), cb0=pB+2*(lane&3);
  {
    const float* pb1=pbg+128;
    #pragma unroll
    for(int bb=0;bb<8;++bb){
      int col=cb0+bb*8;
      zs[rb*128+col]      =c1[bb][0]+pb1[col];
      zs[rb*128+col+1]    =c1[bb][1]+pb1[col+1];
      zs[(rb+8)*128+col]  =c1[bb][2]+pb1[col];
      zs[(rb+8)*128+col+1]=c1[bb][3]+pb1[col+1];
    }
  }
  __syncthreads();
  {
    const float* g=lngg+128; const float* bb=lnbg+128;
    #pragma unroll
    for(int r=0;r<8;++r){
      int row=wid*8+r;
      float4 v=*(const float4*)(zs+row*128+lane*4);
      ln_row_write(v,g,bb,outg+((size_t)b*ROWS+2+row)*Pp,lane);
    }
  }
  __syncthreads();
  {
    const float* pb2=pbg+256;
    #pragma unroll
    for(int bb=0;bb<8;++bb){
      int col=cb0+bb*8;
      zs[rb*128+col]      =c2[bb][0]+pb2[col];
      zs[rb*128+col+1]    =c2[bb][1]+pb2[col+1];
      zs[(rb+8)*128+col]  =c2[bb][2]+pb2[col];
      zs[(rb+8)*128+col+1]=c2[bb][3]+pb2[col+1];
    }
  }
  __syncthreads();
  {
    const float* g=lngg+256; const float* bb=lnbg+256;
    #pragma unroll
    for(int r=0;r<8;++r){
      int row=wid*8+r;
      float4 v=*(const float4*)(zs+row*128+lane*4);
      ln_row_write(v,g,bb,outg+((size_t)b*ROWS+130+row)*Pp,lane);
    }
  }
  if(t<128){
    z5s[t]=z0a0+pbg[t]; z5s[Pp+t]=z0a1+pbg[t];
  }
  if(t<384){
    int j=t>>7, p=t&127;
    z5s[(2+j)*Pp+p]=z3acc+pbg[3*128+p];
  }
  __syncthreads();
  if(wid<5){
    int row=wid, feat=(row<2)?0:3, outrow=(row<2)?row:(256+row);
    float4 v=*(const float4*)(z5s+row*Pp+lane*4);
    ln_row_write(v, lngg+feat*128, lnbg+feat*128,
                 outg+((size_t)b*ROWS+outrow)*Pp, lane);
  }
}

extern "C" void kernel_launch(void* const* d_in, const int* in_sizes, int n_in,
                              void* d_out, int out_size){
  (void)in_sizes;(void)n_in;(void)out_size;
  const float* pwg=(const float*)d_in[7];
  cvt_pw_kernel<<<256,1024>>>(pwg);
  cudaFuncSetAttribute(gpf_kernel, cudaFuncAttributeMaxDynamicSharedMemorySize, gpf::SMEM_BYTES);
  gpf_kernel<<<gpf::Bn, gpf::NT, gpf::SMEM_BYTES>>>(
    (const float*)d_in[0],(const float*)d_in[1],(const float*)d_in[2],(const float*)d_in[3],
    (const float*)d_in[4],(const float*)d_in[5],(const float*)d_in[6],pwg,
    (const float*)d_in[8],(const float*)d_in[9],(const float*)d_in[10],(float*)d_out);
}

// round 13
// speedup vs baseline: 1.2034x; 1.0969x over previous
#include <cuda_runtime.h>
#include <cuda_bf16.h>
#include <cstdint>

namespace gpf {
constexpr int Bn=128, Nn=4096, Pp=128, ROWS=261, TILE=64, NTILES=64, NT=512;
constexpr float W0F=30.f, EPS=1e-5f;
constexpr int SQ=272;   // byte stride: w1 [k][o], q [n][p]
constexpr int SH=144;   // byte stride: h tiles [d][n]
constexpr int BY_W1H=0, BY_W1L=34816;
constexpr int BY_H1H=69632, BY_H1L=BY_H1H+18432, BY_H2H=BY_H1L+18432, BY_H2L=BY_H2H+18432;
constexpr int BY_Q1H=143360, BY_Q1L=BY_Q1H+17408, BY_Q2H=BY_Q1L+17408, BY_Q2L=BY_Q2H+17408;
constexpr int BY_W0=212992, BY_B0=BY_W0+1024, BY_B1=BY_B0+512, BY_W2=BY_B1+512,
  BY_B2=BY_W2+2048, BY_H3=BY_B2+32, BY_Z5=BY_H3+1024;
constexpr int SMEM_BYTES=BY_Z5+2560;  // 220704
}

#define LDSM4T(d,a) asm volatile( \
  "ldmatrix.sync.aligned.m8n8.x4.trans.shared.b16 {%0,%1,%2,%3},[%4];" \
  :"=r"((d)[0]),"=r"((d)[1]),"=r"((d)[2]),"=r"((d)[3]):"r"(a))
#define LDSM4(d,a) asm volatile( \
  "ldmatrix.sync.aligned.m8n8.x4.shared.b16 {%0,%1,%2,%3},[%4];" \
  :"=r"((d)[0]),"=r"((d)[1]),"=r"((d)[2]),"=r"((d)[3]):"r"(a))
#define MMAB(c,a,b0,b1) asm volatile( \
  "mma.sync.aligned.m16n8k16.row.col.f32.bf16.bf16.f32 " \
  "{%0,%1,%2,%3},{%4,%5,%6,%7},{%8,%9},{%0,%1,%2,%3};" \
  :"+f"((c)[0]),"+f"((c)[1]),"+f"((c)[2]),"+f"((c)[3]) \
  :"r"((a)[0]),"r"((a)[1]),"r"((a)[2]),"r"((a)[3]),"r"(b0),"r"(b1))

__device__ __forceinline__ uint32_t smem_u32(const void* p){
  uint32_t a; asm("{ .reg .u64 t; cvta.to.shared.u64 t, %1; cvt.u32.u64 %0, t; }":"=r"(a):"l"(p)); return a;
}
__device__ __forceinline__ uint32_t bfpair(float a, float b, uint32_t& lo){
  __nv_bfloat16 ha=__float2bfloat16(a), hb=__float2bfloat16(b);
  __nv_bfloat162 l; l.x=__float2bfloat16(a-__bfloat162float(ha)); l.y=__float2bfloat16(b-__bfloat162float(hb));
  lo=*(uint32_t*)&l;
  __nv_bfloat162 h; h.x=ha; h.y=hb; return *(uint32_t*)&h;
}
__device__ __forceinline__ void ln_row_write(float4 v, const float* g, const float* bb,
                                             float* orow, int lane){
  float s=(v.x+v.y)+(v.z+v.w);
  #pragma unroll
  for(int o=16;o>0;o>>=1) s+=__shfl_xor_sync(0xffffffffu,s,o);
  float m=s*(1.f/128.f);
  float cx=v.x-m, cy=v.y-m, cz=v.z-m, cw=v.w-m;
  float q=(cx*cx+cy*cy)+(cz*cz+cw*cw);
  #pragma unroll
  for(int o=16;o>0;o>>=1) q+=__shfl_xor_sync(0xffffffffu,q,o);
  float inv=rsqrtf(q*(1.f/128.f)+gpf::EPS);
  float4 gv=*(const float4*)(g+lane*4), bv=*(const float4*)(bb+lane*4);
  float4 ov={cx*inv*gv.x+bv.x, cy*inv*gv.y+bv.y, cz*inv*gv.z+bv.z, cw*inv*gv.w+bv.w};
  *(float4*)(orow+lane*4)=ov;
}

// 3-pass bf16 MMA, PASS-MAJOR interleave (dependent distance = NB8 MMAs).
// A TRANS from [k][m] stride SA; B TRANS from [k][j] stride SB.
template<int KS, int NB8>
__device__ __forceinline__ void gemm3_t(float (*c)[4], uint32_t AH, uint32_t AL,
    uint32_t BH, uint32_t BL, int lane, int m0, int j0, int SA, int SB){
  const int r=lane&7, g=lane>>3;
  const uint32_t ao=(uint32_t)(((g&2)*4+r)*SA + (m0+(g&1)*8)*2);
  const uint32_t bo=(uint32_t)(((g&1)*8+r)*SB + (g>>1)*16 + j0*2);
  #pragma unroll
  for(int kk=0;kk<KS;++kk){
    uint32_t ah[4], al[4];
    LDSM4T(ah, AH+kk*16*SA+ao); LDSM4T(al, AL+kk*16*SA+ao);
    uint32_t bh[NB8/2][4], bl[NB8/2][4];
    #pragma unroll
    for(int b2=0;b2<NB8/2;++b2){
      uint32_t cb=(uint32_t)(kk*16*SB)+bo+b2*32;
      LDSM4T(bh[b2], BH+cb); LDSM4T(bl[b2], BL+cb);
    }
    #pragma unroll
    for(int b2=0;b2<NB8/2;++b2){ MMAB(c[2*b2],ah,bh[b2][0],bh[b2][1]); MMAB(c[2*b2+1],ah,bh[b2][2],bh[b2][3]); }
    #pragma unroll
    for(int b2=0;b2<NB8/2;++b2){ MMAB(c[2*b2],ah,bl[b2][0],bl[b2][1]); MMAB(c[2*b2+1],ah,bl[b2][2],bl[b2][3]); }
    #pragma unroll
    for(int b2=0;b2<NB8/2;++b2){ MMAB(c[2*b2],al,bh[b2][0],bh[b2][1]); MMAB(c[2*b2+1],al,bh[b2][2],bh[b2][3]); }
  }
}
// Same, A NON-TRANS from [m][k] stride SA.
template<int KS, int NB8>
__device__ __forceinline__ void gemm3_nt(float (*c)[4], uint32_t AH, uint32_t AL,
    uint32_t BH, uint32_t BL, int lane, int m0, int j0, int SA, int SB){
  const int r=lane&7, g=lane>>3;
  const uint32_t ao=(uint32_t)((m0+(g&1)*8+r)*SA + (g&2)*8);
  const uint32_t bo=(uint32_t)(((g&1)*8+r)*SB + (g>>1)*16 + j0*2);
  #pragma unroll
  for(int kk=0;kk<KS;++kk){
    uint32_t ah[4], al[4];
    LDSM4(ah, AH+kk*32+ao); LDSM4(al, AL+kk*32+ao);
    uint32_t bh[NB8/2][4], bl[NB8/2][4];
    #pragma unroll
    for(int b2=0;b2<NB8/2;++b2){
      uint32_t cb=(uint32_t)(kk*16*SB)+bo+b2*32;
      LDSM4T(bh[b2], BH+cb); LDSM4T(bl[b2], BL+cb);
    }
    #pragma unroll
    for(int b2=0;b2<NB8/2;++b2){ MMAB(c[2*b2],ah,bh[b2][0],bh[b2][1]); MMAB(c[2*b2+1],ah,bh[b2][2],bh[b2][3]); }
    #pragma unroll
    for(int b2=0;b2<NB8/2;++b2){ MMAB(c[2*b2],ah,bl[b2][0],bl[b2][1]); MMAB(c[2*b2+1],ah,bl[b2][2],bl[b2][3]); }
    #pragma unroll
    for(int b2=0;b2<NB8/2;++b2){ MMAB(c[2*b2],al,bh[b2][0],bh[b2][1]); MMAB(c[2*b2+1],al,bh[b2][2],bh[b2][3]); }
  }
}

// ---- pre-kernel: pw1/pw2 -> bf16 hi/lo device globals ----
__device__ __nv_bfloat16 g_pwh[2u*4096u*128u];
__device__ __nv_bfloat16 g_pwl[2u*4096u*128u];
__global__ void cvt_pw_kernel(const float* __restrict__ pwg){
  unsigned i=blockIdx.x*blockDim.x+threadIdx.x;           // 262144 threads, 4 floats each
  float4 v=((const float4*)(pwg+524288))[i];              // feats 1,2 contiguous
  uint32_t l0,h0,l1,h1;
  h0=bfpair(v.x,v.y,l0); h1=bfpair(v.z,v.w,l1);
  ((uint2*)g_pwh)[i]=make_uint2(h0,h1);
  ((uint2*)g_pwl)[i]=make_uint2(l0,l1);
}

__global__ __launch_bounds__(gpf::NT,1)
void gpf_kernel(const float* __restrict__ w0g, const float* __restrict__ w1g,
                const float* __restrict__ w2g, const float* __restrict__ b0g,
                const float* __restrict__ b1g, const float* __restrict__ b2g,
                const float* __restrict__ xg,  const float* __restrict__ pwg,
                const float* __restrict__ pbg, const float* __restrict__ lngg,
                const float* __restrict__ lnbg, float* __restrict__ outg){
  using namespace gpf;
  extern __shared__ char smc[];
  const int b=blockIdx.x, t=threadIdx.x, lane=t&31, wid=t>>5;
  char *w1h=smc+BY_W1H, *w1l=smc+BY_W1L;
  char *h1h=smc+BY_H1H, *h1l=smc+BY_H1L, *h2h=smc+BY_H2H, *h2l=smc+BY_H2L;
  char *q1h=smc+BY_Q1H, *q1l=smc+BY_Q1L, *q2h=smc+BY_Q2H, *q2l=smc+BY_Q2L;
  float* w0s=(float*)(smc+BY_W0); float* b0s=(float*)(smc+BY_B0); float* b1s=(float*)(smc+BY_B1);
  float* w2s=(float*)(smc+BY_W2); float* b2s=(float*)(smc+BY_B2);
  float* h3s=(float*)(smc+BY_H3); float* z5s=(float*)(smc+BY_Z5);
  const uint32_t W1H=smem_u32(w1h), W1L=smem_u32(w1l);
  const uint32_t H1H=smem_u32(h1h), H1L=smem_u32(h1l), H2H=smem_u32(h2h), H2L=smem_u32(h2l);
  const uint32_t Q1H=smem_u32(q1h), Q1L=smem_u32(q1l), Q2H=smem_u32(q2h), Q2L=smem_u32(q2l);

  { // one-time: w1 -> bf16 hi/lo [k][o]; params
    int po=t&63, k0=t>>6;
    #pragma unroll
    for(int it=0;it<16;++it){
      int k=k0+it*8;
      float2 v=*(const float2*)(w1g+(size_t)b*16384+k*128+2*po);
      uint32_t lo, hi=bfpair(v.x,v.y,lo);
      *(uint32_t*)(w1h+k*SQ+po*4)=hi; *(uint32_t*)(w1l+k*SQ+po*4)=lo;
    }
    if(t<256) w0s[t]=w0g[b*256+t];
    else if(t<384) b0s[t-256]=b0g[b*128+(t-256)];
    else b1s[t-384]=b1g[b*128+(t-384)];
    if(t<128){
      w2s[t*4+0]=w2g[b*384+t*3+0]; w2s[t*4+1]=w2g[b*384+t*3+1]; w2s[t*4+2]=w2g[b*384+t*3+2];
    }
    if(t<3) b2s[t]=b2g[b*3+t];
  }

  float c1[8][4], c2[8][4];
  #pragma unroll
  for(int i=0;i<8;++i){ c1[i][0]=c1[i][1]=c1[i][2]=c1[i][3]=0.f; c2[i][0]=c2[i][1]=c2[i][2]=c2[i][3]=0.f; }
  float z3acc=0.f, z0a0=0.f, z0a1=0.f;
  const int d0w=(wid&7)*16, pB=(wid>>3)*64;   // C/D: 16d x 64p per warp
  const int oB=(wid&7)*16, nC=(wid>>3)*32;    // B:   16o x 32n per warp
  const int npf=t>>3, seg=t&7;                // q-copy mapping (64 rows x 8 segs of 32B)
  const uint4* GH=(const uint4*)g_pwh;
  const uint4* GL=(const uint4*)g_pwl;

  for(int tile=0; tile<NTILES; ++tile){
    const int n0=tile*TILE;
    __syncthreads();

    { // Phase A: copy pre-converted q tiles (gmem bf16, L2-hot); h1 = sin(...) -> [d][n]
      size_t i1=(size_t)(n0+npf)*16 + seg*2;
      { char* d=q1h+npf*SQ+seg*32; uint4 a=GH[i1],     b2=GH[i1+1];     *(uint4*)d=a; *(uint4*)(d+16)=b2; }
      { char* d=q1l+npf*SQ+seg*32; uint4 a=GL[i1],     b2=GL[i1+1];     *(uint4*)d=a; *(uint4*)(d+16)=b2; }
      { char* d=q2h+npf*SQ+seg*32; uint4 a=GH[i1+65536],b2=GH[i1+65537];*(uint4*)d=a; *(uint4*)(d+16)=b2; }
      { char* d=q2l+npf*SQ+seg*32; uint4 a=GL[i1+65536],b2=GL[i1+65537];*(uint4*)d=a; *(uint4*)(d+16)=b2; }
      float4 xv=*(const float4*)(xg+(size_t)n0*2+lane*4);
      #pragma unroll
      for(int it=0;it<8;++it){
        int d=wid+it*16;
        float wa=w0s[d], wb=w0s[128+d], bi=b0s[d];
        float s0=__sinf(W0F*fmaf(xv.x,wa,fmaf(xv.y,wb,bi)));
        float s1=__sinf(W0F*fmaf(xv.z,wa,fmaf(xv.w,wb,bi)));
        uint32_t lo, hi=bfpair(s0,s1,lo);
        *(uint32_t*)(h1h+d*SH+lane*4)=hi; *(uint32_t*)(h1l+d*SH+lane*4)=lo;
      }
    }
    __syncthreads();

    { // Phase B (HMMA): h2^T[o][n] = sin(30*(w1^T h1 + b1))
      float c[4][4];
      #pragma unroll
      for(int i=0;i<4;++i){ c[i][0]=c[i][1]=c[i][2]=c[i][3]=0.f; }
      gemm3_t<8,4>(c, W1H,W1L, H1H,H1L, lane, oB, nC, SQ, SH);
      int o0=oB+(lane>>2);
      float bia0=b1s[o0], bia1=b1s[o0+8];
      #pragma unroll
      for(int bb=0;bb<4;++bb){
        int n=nC+(bb>>1)*16+(bb&1)*8+2*(lane&3);
        float s0=__sinf(W0F*(c[bb][0]+bia0)), s1=__sinf(W0F*(c[bb][1]+bia0));
        float s2=__sinf(W0F*(c[bb][2]+bia1)), s3=__sinf(W0F*(c[bb][3]+bia1));
        uint32_t lo0, hi0=bfpair(s0,s1,lo0);
        uint32_t lo1, hi1=bfpair(s2,s3,lo1);
        *(uint32_t*)(h2h+o0*SH+n*2)=hi0;     *(uint32_t*)(h2l+o0*SH+n*2)=lo0;
        *(uint32_t*)(h2h+(o0+8)*SH+n*2)=hi1; *(uint32_t*)(h2l+(o0+8)*SH+n*2)=lo1;
      }
    }
    // Phase C: z1 += h1^T @ pw1
    gemm3_nt<4,8>(c1, H1H,H1L, Q1H,Q1L, lane, d0w, pB, SH, SQ);
    __syncthreads();

    // Phase E (warps 10-15): h3[n][j] from h2^T
    if(t>=320){
      int u=t-320, n=u/3, j=u-n*3;
      float acc=b2s[j];
      #pragma unroll 8
      for(int o=0;o<128;++o){
        float hv=__bfloat162float(*(__nv_bfloat16*)(h2h+o*SH+n*2));
        float lv=__bfloat162float(*(__nv_bfloat16*)(h2l+o*SH+n*2));
        acc=fmaf(hv+lv, w2s[o*4+j], acc);
      }
      h3s[n*4+j]=acc;
    }
    // Phase D: z2 += h2^T @ pw2
    gemm3_nt<4,8>(c2, H2H,H2L, Q2H,Q2L, lane, d0w, pB, SH, SQ);
    __syncthreads();

    if(t<384){ // z3 += h3^T @ pw3
      int j=t>>7, p=t&127;
      const float* pw3=pwg+(size_t)3*Nn*Pp+(size_t)n0*Pp+p;
      float ta=0.f, tb=0.f;
      #pragma unroll 8
      for(int n=0;n<TILE;n+=2){
        ta=fmaf(h3s[n*4+j],     pw3[n*Pp],     ta);
        tb=fmaf(h3s[(n+1)*4+j], pw3[(n+1)*Pp], tb);
      }
      z3acc+=ta+tb;
    } else { // z0 partial
      int p=t-384;
      const float* pw0=pwg+(size_t)n0*Pp+p;
      const float* xp=xg+n0*2;
      float a0=0.f, a1=0.f;
      #pragma unroll 8
      for(int n=0;n<TILE;++n){ float w=pw0[n*Pp]; a0=fmaf(xp[n*2],w,a0); a1=fmaf(xp[n*2+1],w,a1); }
      z0a0+=a0; z0a1+=a1;
    }
  }

  // ===== epilogue =====
  __syncthreads();
  float* zs=(float*)(smc+BY_H1H);  // h tiles dead: staging
  const int rb=d0w+(lane>>2), cb0=pB+2*(lane&3);
  {
    const float* pb1=pbg+128;
    #pragma unroll
    for(int bb=0;bb<8;++bb){
      int col=cb0+bb*8;
      zs[rb*128+col]      =c1[bb][0]+pb1[col];
      zs[rb*128+col+1]    =c1[bb][1]+pb1[col+1];
      zs[(rb+8)*128+col]  =c1[bb][2]+pb1[col];
      zs[(rb+8)*128+col+1]=c1[bb][3]+pb1[col+1];
    }
  }
  __syncthreads();
  {
    const float* g=lngg+128; const float* bb=lnbg+128;
    #pragma unroll
    for(int r=0;r<8;++r){
      int row=wid*8+r;
      float4 v=*(const float4*)(zs+row*128+lane*4);
      ln_row_write(v,g,bb,outg+((size_t)b*ROWS+2+row)*Pp,lane);
    }
  }
  __syncthreads();
  {
    const float* pb2=pbg+256;
    #pragma unroll
    for(int bb=0;bb<8;++bb){
      int col=cb0+bb*8;
      zs[rb*128+col]      =c2[bb][0]+pb2[col];
      zs[rb*128+col+1]    =c2[bb][1]+pb2[col+1];
      zs[(rb+8)*128+col]  =c2[bb][2]+pb2[col];
      zs[(rb+8)*128+col+1]=c2[bb][3]+pb2[col+1];
    }
  }
  __syncthreads();
  {
    const float* g=lngg+256; const float* bb=lnbg+256;
    #pragma unroll
    for(int r=0;r<8;++r){
      int row=wid*8+r;
      float4 v=*(const float4*)(zs+row*128+lane*4);
      ln_row_write(v,g,bb,outg+((size_t)b*ROWS+130+row)*Pp,lane);
    }
  }
  if(t>=384){
    int p=t-384;
    z5s[p]=z0a0+pbg[p]; z5s[Pp+p]=z0a1+pbg[p];
  }
  if(t<384){
    int j=t>>7, p=t&127;
    z5s[(2+j)*Pp+p]=z3acc+pbg[3*128+p];
  }
  __syncthreads();
  if(wid<5){
    int row=wid, feat=(row<2)?0:3, outrow=(row<2)?row:(256+row);
    float4 v=*(const float4*)(z5s+row*Pp+lane*4);
    ln_row_write(v, lngg+feat*128, lnbg+feat*128,
                 outg+((size_t)b*ROWS+outrow)*Pp, lane);
  }
}

extern "C" void kernel_launch(void* const* d_in, const int* in_sizes, int n_in,
                              void* d_out, int out_size){
  (void)in_sizes;(void)n_in;(void)out_size;
  const float* pwg=(const float*)d_in[7];
  cvt_pw_kernel<<<256,1024>>>(pwg);
  cudaFuncSetAttribute(gpf_kernel, cudaFuncAttributeMaxDynamicSharedMemorySize, gpf::SMEM_BYTES);
  gpf_kernel<<<gpf::Bn, gpf::NT, gpf::SMEM_BYTES>>>(
    (const float*)d_in[0],(const float*)d_in[1],(const float*)d_in[2],(const float*)d_in[3],
    (const float*)d_in[4],(const float*)d_in[5],(const float*)d_in[6],pwg,
    (const float*)d_in[8],(const float*)d_in[9],(const float*)d_in[10],(float*)d_out);
}

// round 14
// speedup vs baseline: 1.2344x; 1.0258x over previous
#include <cuda_runtime.h>
#include <cuda_bf16.h>
#include <cstdint>

namespace gpf {
constexpr int Bn=128, Nn=4096, Pp=128, ROWS=261, TILE=64, NTILES=64, NT=512;
constexpr float W0F=30.f, EPS=1e-5f;
constexpr int SQ=272;   // byte stride: w1 [k][o], q [n][p]
constexpr int SH=144;   // byte stride: h tiles [d][n]
constexpr int BY_W1H=0, BY_W1L=34816;
constexpr int BY_H1H=69632, BY_H1L=BY_H1H+18432, BY_H2H=BY_H1L+18432, BY_H2L=BY_H2H+18432;
constexpr int BY_Q1H=143360, BY_Q1L=BY_Q1H+17408, BY_Q2H=BY_Q1L+17408, BY_Q2L=BY_Q2H+17408;
constexpr int BY_W0=212992, BY_B0=BY_W0+1024, BY_B1=BY_B0+512, BY_W2=BY_B1+512,
  BY_B2=BY_W2+2048, BY_H3=BY_B2+32, BY_Z5=BY_H3+1024;
constexpr int SMEM_BYTES=BY_Z5+1536;  // 219680
}

#define LDSM4T(d,a) asm volatile( \
  "ldmatrix.sync.aligned.m8n8.x4.trans.shared.b16 {%0,%1,%2,%3},[%4];" \
  :"=r"((d)[0]),"=r"((d)[1]),"=r"((d)[2]),"=r"((d)[3]):"r"(a))
#define LDSM4(d,a) asm volatile( \
  "ldmatrix.sync.aligned.m8n8.x4.shared.b16 {%0,%1,%2,%3},[%4];" \
  :"=r"((d)[0]),"=r"((d)[1]),"=r"((d)[2]),"=r"((d)[3]):"r"(a))
#define MMAB(c,a,b0,b1) asm volatile( \
  "mma.sync.aligned.m16n8k16.row.col.f32.bf16.bf16.f32 " \
  "{%0,%1,%2,%3},{%4,%5,%6,%7},{%8,%9},{%0,%1,%2,%3};" \
  :"+f"((c)[0]),"+f"((c)[1]),"+f"((c)[2]),"+f"((c)[3]) \
  :"r"((a)[0]),"r"((a)[1]),"r"((a)[2]),"r"((a)[3]),"r"(b0),"r"(b1))

__device__ __forceinline__ uint32_t smem_u32(const void* p){
  uint32_t a; asm("{ .reg .u64 t; cvta.to.shared.u64 t, %1; cvt.u32.u64 %0, t; }":"=r"(a):"l"(p)); return a;
}
__device__ __forceinline__ uint32_t bfpair(float a, float b, uint32_t& lo){
  __nv_bfloat16 ha=__float2bfloat16(a), hb=__float2bfloat16(b);
  __nv_bfloat162 l; l.x=__float2bfloat16(a-__bfloat162float(ha)); l.y=__float2bfloat16(b-__bfloat162float(hb));
  lo=*(uint32_t*)&l;
  __nv_bfloat162 h; h.x=ha; h.y=hb; return *(uint32_t*)&h;
}
__device__ __forceinline__ void ln_row_write(float4 v, const float* g, const float* bb,
                                             float* orow, int lane){
  float s=(v.x+v.y)+(v.z+v.w);
  #pragma unroll
  for(int o=16;o>0;o>>=1) s+=__shfl_xor_sync(0xffffffffu,s,o);
  float m=s*(1.f/128.f);
  float cx=v.x-m, cy=v.y-m, cz=v.z-m, cw=v.w-m;
  float q=(cx*cx+cy*cy)+(cz*cz+cw*cw);
  #pragma unroll
  for(int o=16;o>0;o>>=1) q+=__shfl_xor_sync(0xffffffffu,q,o);
  float inv=rsqrtf(q*(1.f/128.f)+gpf::EPS);
  float4 gv=*(const float4*)(g+lane*4), bv=*(const float4*)(bb+lane*4);
  float4 ov={cx*inv*gv.x+bv.x, cy*inv*gv.y+bv.y, cz*inv*gv.z+bv.z, cw*inv*gv.w+bv.w};
  *(float4*)(orow+lane*4)=ov;
}

// 3-pass bf16 MMA (accumulator-major, R10 order). A TRANS [k][m]; B TRANS [k][j].
template<int KS, int NB8>
__device__ __forceinline__ void gemm3_t(float (*c)[4], uint32_t AH, uint32_t AL,
    uint32_t BH, uint32_t BL, int lane, int m0, int j0, int SA, int SB){
  const int r=lane&7, g=lane>>3;
  const uint32_t ao=(uint32_t)(((g&2)*4+r)*SA + (m0+(g&1)*8)*2);
  const uint32_t bo=(uint32_t)(((g&1)*8+r)*SB + (g>>1)*16 + j0*2);
  #pragma unroll
  for(int kk=0;kk<KS;++kk){
    uint32_t ah[4], al[4];
    LDSM4T(ah, AH+kk*16*SA+ao); LDSM4T(al, AL+kk*16*SA+ao);
    #pragma unroll
    for(int b2=0;b2<NB8/2;++b2){
      uint32_t bh[4], bl[4], cb=(uint32_t)(kk*16*SB)+bo+b2*32;
      LDSM4T(bh, BH+cb); LDSM4T(bl, BL+cb);
      MMAB(c[2*b2],ah,bh[0],bh[1]); MMAB(c[2*b2],ah,bl[0],bl[1]); MMAB(c[2*b2],al,bh[0],bh[1]);
      MMAB(c[2*b2+1],ah,bh[2],bh[3]); MMAB(c[2*b2+1],ah,bl[2],bl[3]); MMAB(c[2*b2+1],al,bh[2],bh[3]);
    }
  }
}
// Same, A NON-TRANS [m][k].
template<int KS, int NB8>
__device__ __forceinline__ void gemm3_nt(float (*c)[4], uint32_t AH, uint32_t AL,
    uint32_t BH, uint32_t BL, int lane, int m0, int j0, int SA, int SB){
  const int r=lane&7, g=lane>>3;
  const uint32_t ao=(uint32_t)((m0+(g&1)*8+r)*SA + (g&2)*8);
  const uint32_t bo=(uint32_t)(((g&1)*8+r)*SB + (g>>1)*16 + j0*2);
  #pragma unroll
  for(int kk=0;kk<KS;++kk){
    uint32_t ah[4], al[4];
    LDSM4(ah, AH+kk*32+ao); LDSM4(al, AL+kk*32+ao);
    #pragma unroll
    for(int b2=0;b2<NB8/2;++b2){
      uint32_t bh[4], bl[4], cb=(uint32_t)(kk*16*SB)+bo+b2*32;
      LDSM4T(bh, BH+cb); LDSM4T(bl, BL+cb);
      MMAB(c[2*b2],ah,bh[0],bh[1]); MMAB(c[2*b2],ah,bl[0],bl[1]); MMAB(c[2*b2],al,bh[0],bh[1]);
      MMAB(c[2*b2+1],ah,bh[2],bh[3]); MMAB(c[2*b2+1],ah,bl[2],bl[3]); MMAB(c[2*b2+1],al,bh[2],bh[3]);
    }
  }
}

// ---- z0 kernel: rows 0,1 are identical for all b (x is broadcast) ----
__global__ void z0_kernel(const float* __restrict__ xg, const float* __restrict__ pwg,
                          const float* __restrict__ pbg, const float* __restrict__ lngg,
                          const float* __restrict__ lnbg, float* __restrict__ outg){
  __shared__ float z[2][128];
  int t=threadIdx.x, d=t>>7, p=t&127, lane=t&31;
  float acc=0.f;
  #pragma unroll 8
  for(int n=0;n<gpf::Nn;++n) acc=fmaf(xg[n*2+d], pwg[(size_t)n*gpf::Pp+p], acc);
  z[d][p]=acc+pbg[p];
  __syncthreads();
  int wid=t>>5;
  for(int pair=wid; pair<256; pair+=8){
    int row=pair&1, b=pair>>1;
    float4 v=*(const float4*)(&z[row][lane*4]);
    ln_row_write(v, lngg, lnbg, outg+((size_t)b*gpf::ROWS+row)*gpf::Pp, lane);
  }
}

__global__ __launch_bounds__(gpf::NT,1)
void gpf_kernel(const float* __restrict__ w0g, const float* __restrict__ w1g,
                const float* __restrict__ w2g, const float* __restrict__ b0g,
                const float* __restrict__ b1g, const float* __restrict__ b2g,
                const float* __restrict__ xg,  const float* __restrict__ pwg,
                const float* __restrict__ pbg, const float* __restrict__ lngg,
                const float* __restrict__ lnbg, float* __restrict__ outg){
  using namespace gpf;
  extern __shared__ char smc[];
  const int b=blockIdx.x, t=threadIdx.x, lane=t&31, wid=t>>5;
  char *w1h=smc+BY_W1H, *w1l=smc+BY_W1L;
  char *h1h=smc+BY_H1H, *h1l=smc+BY_H1L, *h2h=smc+BY_H2H, *h2l=smc+BY_H2L;
  char *q1h=smc+BY_Q1H, *q1l=smc+BY_Q1L, *q2h=smc+BY_Q2H, *q2l=smc+BY_Q2L;
  float* w0s=(float*)(smc+BY_W0); float* b0s=(float*)(smc+BY_B0); float* b1s=(float*)(smc+BY_B1);
  float* w2s=(float*)(smc+BY_W2); float* b2s=(float*)(smc+BY_B2);
  float* h3s=(float*)(smc+BY_H3); float* z5s=(float*)(smc+BY_Z5);
  const uint32_t W1H=smem_u32(w1h), W1L=smem_u32(w1l);
  const uint32_t H1H=smem_u32(h1h), H1L=smem_u32(h1l), H2H=smem_u32(h2h), H2L=smem_u32(h2l);
  const uint32_t Q1H=smem_u32(q1h), Q1L=smem_u32(q1l), Q2H=smem_u32(q2h), Q2L=smem_u32(q2l);
  const int p2=t&63, nq0=t>>6;

  // convert one pw tile -> bf16 hi/lo [n][p] smem
  auto conv_q=[&](const float* src, char* dh, char* dl, int n0){
    #pragma unroll
    for(int it=0;it<8;++it){
      int n2=nq0+it*8;
      float2 v=*(const float2*)(src+(size_t)(n0+n2)*Pp+2*p2);
      uint32_t lo, hi=bfpair(v.x,v.y,lo);
      *(uint32_t*)(dh+n2*SQ+p2*4)=hi; *(uint32_t*)(dl+n2*SQ+p2*4)=lo;
    }
  };
  // h1 = sin(30*(x@w0+b0)) -> [d][n] bf16 hi/lo
  auto h1_compute=[&](int n0){
    float4 xv=*(const float4*)(xg+(size_t)n0*2+lane*4);
    #pragma unroll
    for(int it=0;it<8;++it){
      int d=wid+it*16;
      float wa=w0s[d], wb=w0s[128+d], bi=b0s[d];
      float s0=__sinf(W0F*fmaf(xv.x,wa,fmaf(xv.y,wb,bi)));
      float s1=__sinf(W0F*fmaf(xv.z,wa,fmaf(xv.w,wb,bi)));
      uint32_t lo, hi=bfpair(s0,s1,lo);
      *(uint32_t*)(h1h+d*SH+lane*4)=hi; *(uint32_t*)(h1l+d*SH+lane*4)=lo;
    }
  };

  { // one-time: w1 -> bf16 hi/lo [k][o]; params
    int po=t&63, k0=t>>6;
    #pragma unroll
    for(int it=0;it<16;++it){
      int k=k0+it*8;
      float2 v=*(const float2*)(w1g+(size_t)b*16384+k*128+2*po);
      uint32_t lo, hi=bfpair(v.x,v.y,lo);
      *(uint32_t*)(w1h+k*SQ+po*4)=hi; *(uint32_t*)(w1l+k*SQ+po*4)=lo;
    }
    if(t<256) w0s[t]=w0g[b*256+t];
    else if(t<384) b0s[t-256]=b0g[b*128+(t-256)];
    else b1s[t-384]=b1g[b*128+(t-384)];
    if(t<128){
      w2s[t*4+0]=w2g[b*384+t*3+0]; w2s[t*4+1]=w2g[b*384+t*3+1]; w2s[t*4+2]=w2g[b*384+t*3+2];
    }
    if(t<3) b2s[t]=b2g[b*3+t];
  }
  __syncthreads();  // w0s/b0s ready for prologue h1

  float c1[8][4], c2[8][4];
  #pragma unroll
  for(int i=0;i<8;++i){ c1[i][0]=c1[i][1]=c1[i][2]=c1[i][3]=0.f; c2[i][0]=c2[i][1]=c2[i][2]=c2[i][3]=0.f; }
  float z3acc=0.f;
  const int d0w=(wid&7)*16, pB=(wid>>3)*64;   // C/D: 16d x 64p per warp
  const int oB=(wid&7)*16, nC=(wid>>3)*32;    // B:   16o x 32n per warp
  const float* pw1src=pwg+(size_t)1*Nn*Pp;
  const float* pw2src=pwg+(size_t)2*Nn*Pp;
  const float* pw3src=pwg+(size_t)3*Nn*Pp;

  // prologue: tile 0 inputs
  conv_q(pw1src, q1h,q1l, 0);
  h1_compute(0);
  __syncthreads();

  for(int tile=0; tile<NTILES; ++tile){
    const int n0=tile*TILE;

    // ===== region 1: conv q2(t); B(t); C(t); F(t-1) =====
    conv_q(pw2src, q2h,q2l, n0);
    { // Phase B (HMMA): h2^T[o][n] = sin(30*(w1^T h1 + b1))
      float c[4][4];
      #pragma unroll
      for(int i=0;i<4;++i){ c[i][0]=c[i][1]=c[i][2]=c[i][3]=0.f; }
      gemm3_t<8,4>(c, W1H,W1L, H1H,H1L, lane, oB, nC, SQ, SH);
      int o0=oB+(lane>>2);
      float bia0=b1s[o0], bia1=b1s[o0+8];
      #pragma unroll
      for(int bb=0;bb<4;++bb){
        int n=nC+(bb>>1)*16+(bb&1)*8+2*(lane&3);
        float s0=__sinf(W0F*(c[bb][0]+bia0)), s1=__sinf(W0F*(c[bb][1]+bia0));
        float s2=__sinf(W0F*(c[bb][2]+bia1)), s3=__sinf(W0F*(c[bb][3]+bia1));
        uint32_t lo0, hi0=bfpair(s0,s1,lo0);
        uint32_t lo1, hi1=bfpair(s2,s3,lo1);
        *(uint32_t*)(h2h+o0*SH+n*2)=hi0;     *(uint32_t*)(h2l+o0*SH+n*2)=lo0;
        *(uint32_t*)(h2h+(o0+8)*SH+n*2)=hi1; *(uint32_t*)(h2l+(o0+8)*SH+n*2)=lo1;
      }
    }
    // Phase C: z1 += h1^T @ pw1
    gemm3_nt<4,8>(c1, H1H,H1L, Q1H,Q1L, lane, d0w, pB, SH, SQ);
    // Phase F(t-1): z3 += h3^T @ pw3 (h3s from previous tile's E)
    if(tile>0 && t<384){
      int j=t>>7, p=t&127;
      const float* pw3=pw3src+(size_t)(n0-TILE)*Pp+p;
      float ta=0.f, tb=0.f;
      #pragma unroll 8
      for(int n=0;n<TILE;n+=2){
        ta=fmaf(h3s[n*4+j],     pw3[n*Pp],     ta);
        tb=fmaf(h3s[(n+1)*4+j], pw3[(n+1)*Pp], tb);
      }
      z3acc+=ta+tb;
    }
    __syncthreads();

    // ===== region 2: E(t); D(t); conv q1(t+1); h1(t+1) =====
    if(t>=320){ // Phase E (warps 10-15): h3[n][j] from h2^T
      int u=t-320, n=u/3, j=u-n*3;
      float acc=b2s[j];
      #pragma unroll 8
      for(int o=0;o<128;++o){
        float hv=__bfloat162float(*(__nv_bfloat16*)(h2h+o*SH+n*2));
        float lv=__bfloat162float(*(__nv_bfloat16*)(h2l+o*SH+n*2));
        acc=fmaf(hv+lv, w2s[o*4+j], acc);
      }
      h3s[n*4+j]=acc;
    }
    // Phase D: z2 += h2^T @ pw2
    gemm3_nt<4,8>(c2, H2H,H2L, Q2H,Q2L, lane, d0w, pB, SH, SQ);
    if(tile+1<NTILES){
      conv_q(pw1src, q1h,q1l, n0+TILE);
      h1_compute(n0+TILE);
    }
    __syncthreads();
  }

  // final F(63)
  if(t<384){
    int j=t>>7, p=t&127;
    const float* pw3=pw3src+(size_t)(NTILES-1)*TILE*Pp+p;
    float ta=0.f, tb=0.f;
    #pragma unroll 8
    for(int n=0;n<TILE;n+=2){
      ta=fmaf(h3s[n*4+j],     pw3[n*Pp],     ta);
      tb=fmaf(h3s[(n+1)*4+j], pw3[(n+1)*Pp], tb);
    }
    z3acc+=ta+tb;
  }

  // ===== epilogue =====
  __syncthreads();
  float* zs=(float*)(smc+BY_H1H);  // h tiles dead: staging
  const int rb=d0w+(lane>>2), cb0=pB+2*(lane&3);
  {
    const float* pb1=pbg+128;
    #pragma unroll
    for(int bb=0;bb<8;++bb){
      int col=cb0+bb*8;
      zs[rb*128+col]      =c1[bb][0]+pb1[col];
      zs[rb*128+col+1]    =c1[bb][1]+pb1[col+1];
      zs[(rb+8)*128+col]  =c1[bb][2]+pb1[col];
      zs[(rb+8)*128+col+1]=c1[bb][3]+pb1[col+1];
    }
  }
  __syncthreads();
  {
    const float* g=lngg+128; const float* bb=lnbg+128;
    #pragma unroll
    for(int r=0;r<8;++r){
      int row=wid*8+r;
      float4 v=*(const float4*)(zs+row*128+lane*4);
      ln_row_write(v,g,bb,outg+((size_t)b*ROWS+2+row)*Pp,lane);
    }
  }
  __syncthreads();
  {
    const float* pb2=pbg+256;
    #pragma unroll
    for(int bb=0;bb<8;++bb){
      int col=cb0+bb*8;
      zs[rb*128+col]      =c2[bb][0]+pb2[col];
      zs[rb*128+col+1]    =c2[bb][1]+pb2[col+1];
      zs[(rb+8)*128+col]  =c2[bb][2]+pb2[col];
      zs[(rb+8)*128+col+1]=c2[bb][3]+pb2[col+1];
    }
  }
  __syncthreads();
  {
    const float* g=lngg+256; const float* bb=lnbg+256;
    #pragma unroll
    for(int r=0;r<8;++r){
      int row=wid*8+r;
      float4 v=*(const float4*)(zs+row*128+lane*4);
      ln_row_write(v,g,bb,outg+((size_t)b*ROWS+130+row)*Pp,lane);
    }
  }
  if(t<384){
    int j=t>>7, p=t&127;
    z5s[j*Pp+p]=z3acc+pbg[3*128+p];
  }
  __syncthreads();
  if(wid<3){
    int row=wid;                    // z3 rows -> out rows 258..260
    float4 v=*(const float4*)(z5s+row*Pp+lane*4);
    ln_row_write(v, lngg+3*128, lnbg+3*128,
                 outg+((size_t)b*ROWS+258+row)*Pp, lane);
  }
}

extern "C" void kernel_launch(void* const* d_in, const int* in_sizes, int n_in,
                              void* d_out, int out_size){
  (void)in_sizes;(void)n_in;(void)out_size;
  const float* xg =(const float*)d_in[6];
  const float* pwg=(const float*)d_in[7];
  const float* pbg=(const float*)d_in[8];
  const float* lngg=(const float*)d_in[9];
  const float* lnbg=(const float*)d_in[10];
  float* outg=(float*)d_out;
  z0_kernel<<<1,256>>>(xg, pwg, pbg, lngg, lnbg, outg);
  cudaFuncSetAttribute(gpf_kernel, cudaFuncAttributeMaxDynamicSharedMemorySize, gpf::SMEM_BYTES);
  gpf_kernel<<<gpf::Bn, gpf::NT, gpf::SMEM_BYTES>>>(
    (const float*)d_in[0],(const float*)d_in[1],(const float*)d_in[2],(const float*)d_in[3],
    (const float*)d_in[4],(const float*)d_in[5],xg,pwg,pbg,lngg,lnbg,outg);
}

// round 15
// speedup vs baseline: 1.4443x; 1.1700x over previous
#include <cuda_runtime.h>
#include <cuda_bf16.h>
#include <cstdint>

namespace gpf {
constexpr int Bn=128, Nn=4096, Pp=128, ROWS=261, TILE=64, NTILES=64, NT=512;
constexpr float W0F=30.f, EPS=1e-5f;
constexpr int SQ=272;   // byte stride: w1 [k][o], q [n][p]
constexpr int SH=144;   // byte stride: h tiles [d][n]
constexpr int BY_W1H=0, BY_W1L=34816;
constexpr int BY_H1H=69632, BY_H1L=BY_H1H+18432, BY_H2H=BY_H1L+18432, BY_H2L=BY_H2H+18432;
constexpr int BY_Q1H=143360, BY_Q1L=BY_Q1H+17408, BY_Q2H=BY_Q1L+17408, BY_Q2L=BY_Q2H+17408;
constexpr int BY_W0=212992, BY_B0=BY_W0+1024, BY_B1=BY_B0+512, BY_W2=BY_B1+512,
  BY_B2=BY_W2+2048, BY_H3=BY_B2+32, BY_Z5=BY_H3+1024;
constexpr int SMEM_BYTES=BY_Z5+1536;  // 219680
}

#define LDSM4T(d,a) asm volatile( \
  "ldmatrix.sync.aligned.m8n8.x4.trans.shared.b16 {%0,%1,%2,%3},[%4];" \
  :"=r"((d)[0]),"=r"((d)[1]),"=r"((d)[2]),"=r"((d)[3]):"r"(a))
#define LDSM4(d,a) asm volatile( \
  "ldmatrix.sync.aligned.m8n8.x4.shared.b16 {%0,%1,%2,%3},[%4];" \
  :"=r"((d)[0]),"=r"((d)[1]),"=r"((d)[2]),"=r"((d)[3]):"r"(a))
#define MMAB(c,a,b0,b1) asm volatile( \
  "mma.sync.aligned.m16n8k16.row.col.f32.bf16.bf16.f32 " \
  "{%0,%1,%2,%3},{%4,%5,%6,%7},{%8,%9},{%0,%1,%2,%3};" \
  :"+f"((c)[0]),"+f"((c)[1]),"+f"((c)[2]),"+f"((c)[3]) \
  :"r"((a)[0]),"r"((a)[1]),"r"((a)[2]),"r"((a)[3]),"r"(b0),"r"(b1))

__device__ __forceinline__ uint32_t smem_u32(const void* p){
  uint32_t a; asm("{ .reg .u64 t; cvta.to.shared.u64 t, %1; cvt.u32.u64 %0, t; }":"=r"(a):"l"(p)); return a;
}
__device__ __forceinline__ uint32_t bfpair(float a, float b, uint32_t& lo){
  __nv_bfloat16 ha=__float2bfloat16(a), hb=__float2bfloat16(b);
  __nv_bfloat162 l; l.x=__float2bfloat16(a-__bfloat162float(ha)); l.y=__float2bfloat16(b-__bfloat162float(hb));
  lo=*(uint32_t*)&l;
  __nv_bfloat162 h; h.x=ha; h.y=hb; return *(uint32_t*)&h;
}
__device__ __forceinline__ void ln_row_write(float4 v, const float* g, const float* bb,
                                             float* orow, int lane){
  float s=(v.x+v.y)+(v.z+v.w);
  #pragma unroll
  for(int o=16;o>0;o>>=1) s+=__shfl_xor_sync(0xffffffffu,s,o);
  float m=s*(1.f/128.f);
  float cx=v.x-m, cy=v.y-m, cz=v.z-m, cw=v.w-m;
  float q=(cx*cx+cy*cy)+(cz*cz+cw*cw);
  #pragma unroll
  for(int o=16;o>0;o>>=1) q+=__shfl_xor_sync(0xffffffffu,q,o);
  float inv=rsqrtf(q*(1.f/128.f)+gpf::EPS);
  float4 gv=*(const float4*)(g+lane*4), bv=*(const float4*)(bb+lane*4);
  float4 ov={cx*inv*gv.x+bv.x, cy*inv*gv.y+bv.y, cz*inv*gv.z+bv.z, cw*inv*gv.w+bv.w};
  *(float4*)(orow+lane*4)=ov;
}

// 3-pass bf16 MMA (accumulator-major). A TRANS [k][m]; B TRANS [k][j].
template<int KS, int NB8>
__device__ __forceinline__ void gemm3_t(float (*c)[4], uint32_t AH, uint32_t AL,
    uint32_t BH, uint32_t BL, int lane, int m0, int j0, int SA, int SB){
  const int r=lane&7, g=lane>>3;
  const uint32_t ao=(uint32_t)(((g&2)*4+r)*SA + (m0+(g&1)*8)*2);
  const uint32_t bo=(uint32_t)(((g&1)*8+r)*SB + (g>>1)*16 + j0*2);
  #pragma unroll
  for(int kk=0;kk<KS;++kk){
    uint32_t ah[4], al[4];
    LDSM4T(ah, AH+kk*16*SA+ao); LDSM4T(al, AL+kk*16*SA+ao);
    #pragma unroll
    for(int b2=0;b2<NB8/2;++b2){
      uint32_t bh[4], bl[4], cb=(uint32_t)(kk*16*SB)+bo+b2*32;
      LDSM4T(bh, BH+cb); LDSM4T(bl, BL+cb);
      MMAB(c[2*b2],ah,bh[0],bh[1]); MMAB(c[2*b2],ah,bl[0],bl[1]); MMAB(c[2*b2],al,bh[0],bh[1]);
      MMAB(c[2*b2+1],ah,bh[2],bh[3]); MMAB(c[2*b2+1],ah,bl[2],bl[3]); MMAB(c[2*b2+1],al,bh[2],bh[3]);
    }
  }
}
// Same, A NON-TRANS [m][k].
template<int KS, int NB8>
__device__ __forceinline__ void gemm3_nt(float (*c)[4], uint32_t AH, uint32_t AL,
    uint32_t BH, uint32_t BL, int lane, int m0, int j0, int SA, int SB){
  const int r=lane&7, g=lane>>3;
  const uint32_t ao=(uint32_t)((m0+(g&1)*8+r)*SA + (g&2)*8);
  const uint32_t bo=(uint32_t)(((g&1)*8+r)*SB + (g>>1)*16 + j0*2);
  #pragma unroll
  for(int kk=0;kk<KS;++kk){
    uint32_t ah[4], al[4];
    LDSM4(ah, AH+kk*32+ao); LDSM4(al, AL+kk*32+ao);
    #pragma unroll
    for(int b2=0;b2<NB8/2;++b2){
      uint32_t bh[4], bl[4], cb=(uint32_t)(kk*16*SB)+bo+b2*32;
      LDSM4T(bh, BH+cb); LDSM4T(bl, BL+cb);
      MMAB(c[2*b2],ah,bh[0],bh[1]); MMAB(c[2*b2],ah,bl[0],bl[1]); MMAB(c[2*b2],al,bh[0],bh[1]);
      MMAB(c[2*b2+1],ah,bh[2],bh[3]); MMAB(c[2*b2+1],ah,bl[2],bl[3]); MMAB(c[2*b2+1],al,bh[2],bh[3]);
    }
  }
}

// ---- z0 (rows 0,1 identical for all b since x is broadcast) ----
__device__ float g_z0s[32*256];
__global__ void z0_part(const float* __restrict__ xg, const float* __restrict__ pwg){
  int bk=blockIdx.x, t=threadIdx.x, d=t>>7, p=t&127;
  int n0=bk*128;
  float acc=0.f;
  #pragma unroll 8
  for(int n=0;n<128;++n)
    acc=fmaf(xg[(n0+n)*2+d], pwg[(size_t)(n0+n)*gpf::Pp+p], acc);
  g_z0s[bk*256+t]=acc;
}
__global__ void z0_fin(const float* __restrict__ pbg, const float* __restrict__ lngg,
                       const float* __restrict__ lnbg, float* __restrict__ outg){
  __shared__ float z[2][128];
  int t=threadIdx.x, d=t>>7, p=t&127, lane=t&31, wid=t>>5;
  float acc=0.f;
  #pragma unroll
  for(int k=0;k<32;++k) acc+=g_z0s[k*256+t];
  z[d][p]=acc+pbg[p];
  __syncthreads();
  // LN once per row into smem, then broadcast to all 128 b
  if(wid<2){
    float4 v=*(const float4*)(&z[wid][lane*4]);
    float s=(v.x+v.y)+(v.z+v.w);
    #pragma unroll
    for(int o=16;o>0;o>>=1) s+=__shfl_xor_sync(0xffffffffu,s,o);
    float m=s*(1.f/128.f);
    float cx=v.x-m, cy=v.y-m, cz=v.z-m, cw=v.w-m;
    float q=(cx*cx+cy*cy)+(cz*cz+cw*cw);
    #pragma unroll
    for(int o=16;o>0;o>>=1) q+=__shfl_xor_sync(0xffffffffu,q,o);
    float inv=rsqrtf(q*(1.f/128.f)+gpf::EPS);
    float4 gv=*(const float4*)(lngg+lane*4), bv=*(const float4*)(lnbg+lane*4);
    float4 ov={cx*inv*gv.x+bv.x, cy*inv*gv.y+bv.y, cz*inv*gv.z+bv.z, cw*inv*gv.w+bv.w};
    *(float4*)(&z[wid][lane*4])=ov;
  }
  __syncthreads();
  float4 v0=*(const float4*)(&z[0][ (t&31)*4 ]);
  float4 v1=*(const float4*)(&z[1][ (t&31)*4 ]);
  for(int b=wid; b<gpf::Bn; b+=8){
    *(float4*)(outg+((size_t)b*gpf::ROWS+0)*gpf::Pp+(t&31)*4)=v0;
    *(float4*)(outg+((size_t)b*gpf::ROWS+1)*gpf::Pp+(t&31)*4)=v1;
  }
}

__global__ __launch_bounds__(gpf::NT,1)
void gpf_kernel(const float* __restrict__ w0g, const float* __restrict__ w1g,
                const float* __restrict__ w2g, const float* __restrict__ b0g,
                const float* __restrict__ b1g, const float* __restrict__ b2g,
                const float* __restrict__ xg,  const float* __restrict__ pwg,
                const float* __restrict__ pbg, const float* __restrict__ lngg,
                const float* __restrict__ lnbg, float* __restrict__ outg){
  using namespace gpf;
  extern __shared__ char smc[];
  const int b=blockIdx.x, t=threadIdx.x, lane=t&31, wid=t>>5;
  char *w1h=smc+BY_W1H, *w1l=smc+BY_W1L;
  char *h1h=smc+BY_H1H, *h1l=smc+BY_H1L, *h2h=smc+BY_H2H, *h2l=smc+BY_H2L;
  char *q1h=smc+BY_Q1H, *q1l=smc+BY_Q1L, *q2h=smc+BY_Q2H, *q2l=smc+BY_Q2L;
  float* w0s=(float*)(smc+BY_W0); float* b0s=(float*)(smc+BY_B0); float* b1s=(float*)(smc+BY_B1);
  float* w2s=(float*)(smc+BY_W2); float* b2s=(float*)(smc+BY_B2);
  float* h3s=(float*)(smc+BY_H3); float* z5s=(float*)(smc+BY_Z5);
  const uint32_t W1H=smem_u32(w1h), W1L=smem_u32(w1l);
  const uint32_t H1H=smem_u32(h1h), H1L=smem_u32(h1l), H2H=smem_u32(h2h), H2L=smem_u32(h2l);
  const uint32_t Q1H=smem_u32(q1h), Q1L=smem_u32(q1l), Q2H=smem_u32(q2h), Q2L=smem_u32(q2l);
  const int p2=t&63, nq0=t>>6;

  auto conv_q=[&](const float* src, char* dh, char* dl, int n0){
    #pragma unroll
    for(int it=0;it<8;++it){
      int n2=nq0+it*8;
      float2 v=*(const float2*)(src+(size_t)(n0+n2)*Pp+2*p2);
      uint32_t lo, hi=bfpair(v.x,v.y,lo);
      *(uint32_t*)(dh+n2*SQ+p2*4)=hi; *(uint32_t*)(dl+n2*SQ+p2*4)=lo;
    }
  };
  auto h1_compute=[&](int n0){
    float4 xv=*(const float4*)(xg+(size_t)n0*2+lane*4);
    #pragma unroll
    for(int it=0;it<8;++it){
      int d=wid+it*16;
      float wa=w0s[d], wb=w0s[128+d], bi=b0s[d];
      float s0=__sinf(W0F*fmaf(xv.x,wa,fmaf(xv.y,wb,bi)));
      float s1=__sinf(W0F*fmaf(xv.z,wa,fmaf(xv.w,wb,bi)));
      uint32_t lo, hi=bfpair(s0,s1,lo);
      *(uint32_t*)(h1h+d*SH+lane*4)=hi; *(uint32_t*)(h1l+d*SH+lane*4)=lo;
    }
  };

  { // one-time: w1 -> bf16 hi/lo [k][o]; params
    int po=t&63, k0=t>>6;
    #pragma unroll
    for(int it=0;it<16;++it){
      int k=k0+it*8;
      float2 v=*(const float2*)(w1g+(size_t)b*16384+k*128+2*po);
      uint32_t lo, hi=bfpair(v.x,v.y,lo);
      *(uint32_t*)(w1h+k*SQ+po*4)=hi; *(uint32_t*)(w1l+k*SQ+po*4)=lo;
    }
    if(t<256) w0s[t]=w0g[b*256+t];
    else if(t<384) b0s[t-256]=b0g[b*128+(t-256)];
    else b1s[t-384]=b1g[b*128+(t-384)];
    if(t<128){
      w2s[t*4+0]=w2g[b*384+t*3+0]; w2s[t*4+1]=w2g[b*384+t*3+1]; w2s[t*4+2]=w2g[b*384+t*3+2];
    }
    if(t<3) b2s[t]=b2g[b*3+t];
  }
  __syncthreads();

  float c1[8][4], c2[8][4];
  #pragma unroll
  for(int i=0;i<8;++i){ c1[i][0]=c1[i][1]=c1[i][2]=c1[i][3]=0.f; c2[i][0]=c2[i][1]=c2[i][2]=c2[i][3]=0.f; }
  float z3acc=0.f;
  const int d0w=(wid&7)*16, pB=(wid>>3)*64;   // C/D: 16d x 64p per warp
  const int oB=(wid&7)*16, nC=(wid>>3)*32;    // B:   16o x 32n per warp
  const float* pw1src=pwg+(size_t)1*Nn*Pp;
  const float* pw2src=pwg+(size_t)2*Nn*Pp;
  const float* pw3src=pwg+(size_t)3*Nn*Pp;

  conv_q(pw1src, q1h,q1l, 0);
  h1_compute(0);
  __syncthreads();

  for(int tile=0; tile<NTILES; ++tile){
    const int n0=tile*TILE;

    // ===== region 1: conv q2(t); B(t); C(t); F(t-1) =====
    conv_q(pw2src, q2h,q2l, n0);
    {
      float c[4][4];
      #pragma unroll
      for(int i=0;i<4;++i){ c[i][0]=c[i][1]=c[i][2]=c[i][3]=0.f; }
      gemm3_t<8,4>(c, W1H,W1L, H1H,H1L, lane, oB, nC, SQ, SH);
      int o0=oB+(lane>>2);
      float bia0=b1s[o0], bia1=b1s[o0+8];
      #pragma unroll
      for(int bb=0;bb<4;++bb){
        int n=nC+(bb>>1)*16+(bb&1)*8+2*(lane&3);
        float s0=__sinf(W0F*(c[bb][0]+bia0)), s1=__sinf(W0F*(c[bb][1]+bia0));
        float s2=__sinf(W0F*(c[bb][2]+bia1)), s3=__sinf(W0F*(c[bb][3]+bia1));
        uint32_t lo0, hi0=bfpair(s0,s1,lo0);
        uint32_t lo1, hi1=bfpair(s2,s3,lo1);
        *(uint32_t*)(h2h+o0*SH+n*2)=hi0;     *(uint32_t*)(h2l+o0*SH+n*2)=lo0;
        *(uint32_t*)(h2h+(o0+8)*SH+n*2)=hi1; *(uint32_t*)(h2l+(o0+8)*SH+n*2)=lo1;
      }
    }
    gemm3_nt<4,8>(c1, H1H,H1L, Q1H,Q1L, lane, d0w, pB, SH, SQ);
    if(tile>0 && t<384){
      int j=t>>7, p=t&127;
      const float* pw3=pw3src+(size_t)(n0-TILE)*Pp+p;
      float ta=0.f, tb=0.f;
      #pragma unroll 8
      for(int n=0;n<TILE;n+=2){
        ta=fmaf(h3s[n*4+j],     pw3[n*Pp],     ta);
        tb=fmaf(h3s[(n+1)*4+j], pw3[(n+1)*Pp], tb);
      }
      z3acc+=ta+tb;
    }
    __syncthreads();

    // ===== region 2: E(t); D(t); conv q1(t+1); h1(t+1) =====
    if(t>=320){
      int u=t-320, n=u/3, j=u-n*3;
      float acc=b2s[j];
      #pragma unroll 8
      for(int o=0;o<128;++o){
        float hv=__bfloat162float(*(__nv_bfloat16*)(h2h+o*SH+n*2));
        float lv=__bfloat162float(*(__nv_bfloat16*)(h2l+o*SH+n*2));
        acc=fmaf(hv+lv, w2s[o*4+j], acc);
      }
      h3s[n*4+j]=acc;
    }
    gemm3_nt<4,8>(c2, H2H,H2L, Q2H,Q2L, lane, d0w, pB, SH, SQ);
    if(tile+1<NTILES){
      conv_q(pw1src, q1h,q1l, n0+TILE);
      h1_compute(n0+TILE);
    }
    __syncthreads();
  }

  // final F(63)
  if(t<384){
    int j=t>>7, p=t&127;
    const float* pw3=pw3src+(size_t)(NTILES-1)*TILE*Pp+p;
    float ta=0.f, tb=0.f;
    #pragma unroll 8
    for(int n=0;n<TILE;n+=2){
      ta=fmaf(h3s[n*4+j],     pw3[n*Pp],     ta);
      tb=fmaf(h3s[(n+1)*4+j], pw3[(n+1)*Pp], tb);
    }
    z3acc+=ta+tb;
  }

  // ===== epilogue =====
  __syncthreads();
  float* zs=(float*)(smc+BY_H1H);
  const int rb=d0w+(lane>>2), cb0=pB+2*(lane&3);
  {
    const float* pb1=pbg+128;
    #pragma unroll
    for(int bb=0;bb<8;++bb){
      int col=cb0+bb*8;
      zs[rb*128+col]      =c1[bb][0]+pb1[col];
      zs[rb*128+col+1]    =c1[bb][1]+pb1[col+1];
      zs[(rb+8)*128+col]  =c1[bb][2]+pb1[col];
      zs[(rb+8)*128+col+1]=c1[bb][3]+pb1[col+1];
    }
  }
  __syncthreads();
  {
    const float* g=lngg+128; const float* bb=lnbg+128;
    #pragma unroll
    for(int r=0;r<8;++r){
      int row=wid*8+r;
      float4 v=*(const float4*)(zs+row*128+lane*4);
      ln_row_write(v,g,bb,outg+((size_t)b*ROWS+2+row)*Pp,lane);
    }
  }
  __syncthreads();
  {
    const float* pb2=pbg+256;
    #pragma unroll
    for(int bb=0;bb<8;++bb){
      int col=cb0+bb*8;
      zs[rb*128+col]      =c2[bb][0]+pb2[col];
      zs[rb*128+col+1]    =c2[bb][1]+pb2[col+1];
      zs[(rb+8)*128+col]  =c2[bb][2]+pb2[col];
      zs[(rb+8)*128+col+1]=c2[bb][3]+pb2[col+1];
    }
  }
  __syncthreads();
  {
    const float* g=lngg+256; const float* bb=lnbg+256;
    #pragma unroll
    for(int r=0;r<8;++r){
      int row=wid*8+r;
      float4 v=*(const float4*)(zs+row*128+lane*4);
      ln_row_write(v,g,bb,outg+((size_t)b*ROWS+130+row)*Pp,lane);
    }
  }
  if(t<384){
    int j=t>>7, p=t&127;
    z5s[j*Pp+p]=z3acc+pbg[3*128+p];
  }
  __syncthreads();
  if(wid<3){
    int row=wid;
    float4 v=*(const float4*)(z5s+row*Pp+lane*4);
    ln_row_write(v, lngg+3*128, lnbg+3*128,
                 outg+((size_t)b*ROWS+258+row)*Pp, lane);
  }
}

extern "C" void kernel_launch(void* const* d_in, const int* in_sizes, int n_in,
                              void* d_out, int out_size){
  (void)in_sizes;(void)n_in;(void)out_size;
  const float* xg =(const float*)d_in[6];
  const float* pwg=(const float*)d_in[7];
  const float* pbg=(const float*)d_in[8];
  const float* lngg=(const float*)d_in[9];
  const float* lnbg=(const float*)d_in[10];
  float* outg=(float*)d_out;
  z0_part<<<32,256>>>(xg, pwg);
  cudaFuncSetAttribute(gpf_kernel, cudaFuncAttributeMaxDynamicSharedMemorySize, gpf::SMEM_BYTES);
  gpf_kernel<<<gpf::Bn, gpf::NT, gpf::SMEM_BYTES>>>(
    (const float*)d_in[0],(const float*)d_in[1],(const float*)d_in[2],(const float*)d_in[3],
    (const float*)d_in[4],(const float*)d_in[5],xg,pwg,pbg,lngg,lnbg,outg);
  z0_fin<<<1,256>>>(pbg, lngg, lnbg, outg);
}

// round 16
// speedup vs baseline: 1.4750x; 1.0213x over previous
#include <cuda_runtime.h>
#include <cuda_bf16.h>
#include <cstdint>

namespace gpf {
constexpr int Bn=128, Nn=4096, Pp=128, ROWS=261, TILE=64, NTILES=64, NT=512;
constexpr float W0F=30.f, EPS=1e-5f;
constexpr int SQ=272, SH=144;
constexpr int BY_W1H=0, BY_W1L=34816;
constexpr int BY_H1H=69632, BY_H1L=BY_H1H+18432, BY_H2H=BY_H1L+18432, BY_H2L=BY_H2H+18432;
constexpr int BY_Q1H=143360, BY_Q1L=BY_Q1H+17408, BY_Q2H=BY_Q1L+17408, BY_Q2L=BY_Q2H+17408;
constexpr int BY_W0=212992, BY_B0=BY_W0+1024, BY_B1=BY_B0+512, BY_W2=BY_B1+512,
  BY_B2=BY_W2+2048, BY_H3=BY_B2+32, BY_Z5=BY_H3+1024;
constexpr int SMEM_BYTES=BY_Z5+1536;  // 219680
}

#define LDSM4T(d,a) asm volatile( \
  "ldmatrix.sync.aligned.m8n8.x4.trans.shared.b16 {%0,%1,%2,%3},[%4];" \
  :"=r"((d)[0]),"=r"((d)[1]),"=r"((d)[2]),"=r"((d)[3]):"r"(a))
#define LDSM4(d,a) asm volatile( \
  "ldmatrix.sync.aligned.m8n8.x4.shared.b16 {%0,%1,%2,%3},[%4];" \
  :"=r"((d)[0]),"=r"((d)[1]),"=r"((d)[2]),"=r"((d)[3]):"r"(a))
#define MMAB(c,a,b0,b1) asm volatile( \
  "mma.sync.aligned.m16n8k16.row.col.f32.bf16.bf16.f32 " \
  "{%0,%1,%2,%3},{%4,%5,%6,%7},{%8,%9},{%0,%1,%2,%3};" \
  :"+f"((c)[0]),"+f"((c)[1]),"+f"((c)[2]),"+f"((c)[3]) \
  :"r"((a)[0]),"r"((a)[1]),"r"((a)[2]),"r"((a)[3]),"r"(b0),"r"(b1))

__device__ __forceinline__ uint32_t smem_u32(const void* p){
  uint32_t a; asm("{ .reg .u64 t; cvta.to.shared.u64 t, %1; cvt.u32.u64 %0, t; }":"=r"(a):"l"(p)); return a;
}
__device__ __forceinline__ uint32_t bfpair(float a, float b, uint32_t& lo){
  __nv_bfloat16 ha=__float2bfloat16(a), hb=__float2bfloat16(b);
  __nv_bfloat162 l; l.x=__float2bfloat16(a-__bfloat162float(ha)); l.y=__float2bfloat16(b-__bfloat162float(hb));
  lo=*(uint32_t*)&l;
  __nv_bfloat162 h; h.x=ha; h.y=hb; return *(uint32_t*)&h;
}
__device__ __forceinline__ void ln_row_write(float4 v, const float* g, const float* bb,
                                             float* orow, int lane){
  float s=(v.x+v.y)+(v.z+v.w);
  #pragma unroll
  for(int o=16;o>0;o>>=1) s+=__shfl_xor_sync(0xffffffffu,s,o);
  float m=s*(1.f/128.f);
  float cx=v.x-m, cy=v.y-m, cz=v.z-m, cw=v.w-m;
  float q=(cx*cx+cy*cy)+(cz*cz+cw*cw);
  #pragma unroll
  for(int o=16;o>0;o>>=1) q+=__shfl_xor_sync(0xffffffffu,q,o);
  float inv=rsqrtf(q*(1.f/128.f)+gpf::EPS);
  float4 gv=*(const float4*)(g+lane*4), bv=*(const float4*)(bb+lane*4);
  float4 ov={cx*inv*gv.x+bv.x, cy*inv*gv.y+bv.y, cz*inv*gv.z+bv.z, cw*inv*gv.w+bv.w};
  *(float4*)(orow+lane*4)=ov;
}

// 3-pass bf16 MMA. A TRANS [k][m]; B TRANS [k][j]. (Phase B)
template<int KS, int NB8>
__device__ __forceinline__ void gemm3_t(float (*c)[4], uint32_t AH, uint32_t AL,
    uint32_t BH, uint32_t BL, int lane, int m0, int j0, int SA, int SB){
  const int r=lane&7, g=lane>>3;
  const uint32_t ao=(uint32_t)(((g&2)*4+r)*SA + (m0+(g&1)*8)*2);
  const uint32_t bo=(uint32_t)(((g&1)*8+r)*SB + (g>>1)*16 + j0*2);
  #pragma unroll
  for(int kk=0;kk<KS;++kk){
    uint32_t ah[4], al[4];
    LDSM4T(ah, AH+kk*16*SA+ao); LDSM4T(al, AL+kk*16*SA+ao);
    #pragma unroll
    for(int b2=0;b2<NB8/2;++b2){
      uint32_t bh[4], bl[4], cb=(uint32_t)(kk*16*SB)+bo+b2*32;
      LDSM4T(bh, BH+cb); LDSM4T(bl, BL+cb);
      MMAB(c[2*b2],ah,bh[0],bh[1]); MMAB(c[2*b2],ah,bl[0],bl[1]); MMAB(c[2*b2],al,bh[0],bh[1]);
      MMAB(c[2*b2+1],ah,bh[2],bh[3]); MMAB(c[2*b2+1],ah,bl[2],bl[3]); MMAB(c[2*b2+1],al,bh[2],bh[3]);
    }
  }
}
// 3-pass bf16 MMA, m32 x n32 warp tile. A NON-TRANS [m][k] stride SA; B TRANS [k][j] stride SB.
// c[8][4]: index = mb*4 + nb8 (mb: m16 block 0..1, nb8: n8 block 0..3).
template<int KS>
__device__ __forceinline__ void gemm3_nt32(float (*c)[4], uint32_t AH, uint32_t AL,
    uint32_t BH, uint32_t BL, int lane, int m0, int j0, int SA, int SB){
  const int r=lane&7, g=lane>>3;
  const uint32_t ao0=(uint32_t)((m0+(g&1)*8+r)*SA + (g&2)*8);
  const uint32_t ao1=ao0+(uint32_t)(16*SA);
  const uint32_t bo=(uint32_t)(((g&1)*8+r)*SB + (g>>1)*16 + j0*2);
  #pragma unroll
  for(int kk=0;kk<KS;++kk){
    const uint32_t ka=(uint32_t)(kk*32), kb=(uint32_t)(kk*16*SB);
    uint32_t ah0[4], ah1[4], bh0[4], bh1[4];
    LDSM4(ah0, AH+ka+ao0); LDSM4(ah1, AH+ka+ao1);
    LDSM4T(bh0, BH+kb+bo); LDSM4T(bh1, BH+kb+bo+32);
    // hi*hi
    MMAB(c[0],ah0,bh0[0],bh0[1]); MMAB(c[1],ah0,bh0[2],bh0[3]);
    MMAB(c[2],ah0,bh1[0],bh1[1]); MMAB(c[3],ah0,bh1[2],bh1[3]);
    MMAB(c[4],ah1,bh0[0],bh0[1]); MMAB(c[5],ah1,bh0[2],bh0[3]);
    MMAB(c[6],ah1,bh1[0],bh1[1]); MMAB(c[7],ah1,bh1[2],bh1[3]);
    // hi*lo
    uint32_t bl0[4], bl1[4];
    LDSM4T(bl0, BL+kb+bo); LDSM4T(bl1, BL+kb+bo+32);
    MMAB(c[0],ah0,bl0[0],bl0[1]); MMAB(c[1],ah0,bl0[2],bl0[3]);
    MMAB(c[2],ah0,bl1[0],bl1[1]); MMAB(c[3],ah0,bl1[2],bl1[3]);
    MMAB(c[4],ah1,bl0[0],bl0[1]); MMAB(c[5],ah1,bl0[2],bl0[3]);
    MMAB(c[6],ah1,bl1[0],bl1[1]); MMAB(c[7],ah1,bl1[2],bl1[3]);
    // lo*hi
    uint32_t al0[4], al1[4];
    LDSM4(al0, AL+ka+ao0); LDSM4(al1, AL+ka+ao1);
    MMAB(c[0],al0,bh0[0],bh0[1]); MMAB(c[1],al0,bh0[2],bh0[3]);
    MMAB(c[2],al0,bh1[0],bh1[1]); MMAB(c[3],al0,bh1[2],bh1[3]);
    MMAB(c[4],al1,bh0[0],bh0[1]); MMAB(c[5],al1,bh0[2],bh0[3]);
    MMAB(c[6],al1,bh1[0],bh1[1]); MMAB(c[7],al1,bh1[2],bh1[3]);
  }
}

// ---- z0 (rows 0,1 identical for all b since x is broadcast) ----
__device__ float g_z0s[128*256];
__global__ void z0_part(const float* __restrict__ xg, const float* __restrict__ pwg){
  int bk=blockIdx.x, t=threadIdx.x, d=t>>7, p=t&127;
  int n0=bk*32;
  float acc=0.f;
  #pragma unroll 8
  for(int n=0;n<32;++n)
    acc=fmaf(xg[(n0+n)*2+d], pwg[(size_t)(n0+n)*gpf::Pp+p], acc);
  g_z0s[bk*256+t]=acc;
}
__global__ void z0_fin(const float* __restrict__ pbg, const float* __restrict__ lngg,
                       const float* __restrict__ lnbg, float* __restrict__ outg){
  __shared__ float z[2][128];
  int t=threadIdx.x, d=t>>7, p=t&127, lane=t&31, wid=t>>5;
  float acc=0.f;
  #pragma unroll 8
  for(int k=0;k<128;++k) acc+=g_z0s[k*256+t];
  z[d][p]=acc+pbg[p];
  __syncthreads();
  if(wid<2){
    float4 v=*(const float4*)(&z[wid][lane*4]);
    float s=(v.x+v.y)+(v.z+v.w);
    #pragma unroll
    for(int o=16;o>0;o>>=1) s+=__shfl_xor_sync(0xffffffffu,s,o);
    float m=s*(1.f/128.f);
    float cx=v.x-m, cy=v.y-m, cz=v.z-m, cw=v.w-m;
    float q=(cx*cx+cy*cy)+(cz*cz+cw*cw);
    #pragma unroll
    for(int o=16;o>0;o>>=1) q+=__shfl_xor_sync(0xffffffffu,q,o);
    float inv=rsqrtf(q*(1.f/128.f)+gpf::EPS);
    float4 gv=*(const float4*)(lngg+lane*4), bv=*(const float4*)(lnbg+lane*4);
    float4 ov={cx*inv*gv.x+bv.x, cy*inv*gv.y+bv.y, cz*inv*gv.z+bv.z, cw*inv*gv.w+bv.w};
    *(float4*)(&z[wid][lane*4])=ov;
  }
  __syncthreads();
  float4 v0=*(const float4*)(&z[0][lane*4]);
  float4 v1=*(const float4*)(&z[1][lane*4]);
  for(int b=wid; b<gpf::Bn; b+=8){
    *(float4*)(outg+((size_t)b*gpf::ROWS+0)*gpf::Pp+lane*4)=v0;
    *(float4*)(outg+((size_t)b*gpf::ROWS+1)*gpf::Pp+lane*4)=v1;
  }
}

__global__ __launch_bounds__(gpf::NT,1)
void gpf_kernel(const float* __restrict__ w0g, const float* __restrict__ w1g,
                const float* __restrict__ w2g, const float* __restrict__ b0g,
                const float* __restrict__ b1g, const float* __restrict__ b2g,
                const float* __restrict__ xg,  const float* __restrict__ pwg,
                const float* __restrict__ pbg, const float* __restrict__ lngg,
                const float* __restrict__ lnbg, float* __restrict__ outg){
  using namespace gpf;
  extern __shared__ char smc[];
  const int b=blockIdx.x, t=threadIdx.x, lane=t&31, wid=t>>5;
  char *w1h=smc+BY_W1H, *w1l=smc+BY_W1L;
  char *h1h=smc+BY_H1H, *h1l=smc+BY_H1L, *h2h=smc+BY_H2H, *h2l=smc+BY_H2L;
  char *q1h=smc+BY_Q1H, *q1l=smc+BY_Q1L, *q2h=smc+BY_Q2H, *q2l=smc+BY_Q2L;
  float* w0s=(float*)(smc+BY_W0); float* b0s=(float*)(smc+BY_B0); float* b1s=(float*)(smc+BY_B1);
  float* w2s=(float*)(smc+BY_W2); float* b2s=(float*)(smc+BY_B2);
  float* h3s=(float*)(smc+BY_H3); float* z5s=(float*)(smc+BY_Z5);
  const uint32_t W1H=smem_u32(w1h), W1L=smem_u32(w1l);
  const uint32_t H1H=smem_u32(h1h), H1L=smem_u32(h1l), H2H=smem_u32(h2h), H2L=smem_u32(h2l);
  const uint32_t Q1H=smem_u32(q1h), Q1L=smem_u32(q1l), Q2H=smem_u32(q2h), Q2L=smem_u32(q2l);
  const int p2=t&63, nq0=t>>6;

  auto conv_q=[&](const float* src, char* dh, char* dl, int n0){
    #pragma unroll
    for(int it=0;it<8;++it){
      int n2=nq0+it*8;
      float2 v=*(const float2*)(src+(size_t)(n0+n2)*Pp+2*p2);
      uint32_t lo, hi=bfpair(v.x,v.y,lo);
      *(uint32_t*)(dh+n2*SQ+p2*4)=hi; *(uint32_t*)(dl+n2*SQ+p2*4)=lo;
    }
  };
  auto h1_compute=[&](int n0){
    float4 xv=*(const float4*)(xg+(size_t)n0*2+lane*4);
    #pragma unroll
    for(int it=0;it<8;++it){
      int d=wid+it*16;
      float wa=w0s[d], wb=w0s[128+d], bi=b0s[d];
      float s0=__sinf(W0F*fmaf(xv.x,wa,fmaf(xv.y,wb,bi)));
      float s1=__sinf(W0F*fmaf(xv.z,wa,fmaf(xv.w,wb,bi)));
      uint32_t lo, hi=bfpair(s0,s1,lo);
      *(uint32_t*)(h1h+d*SH+lane*4)=hi; *(uint32_t*)(h1l+d*SH+lane*4)=lo;
    }
  };

  { // one-time: w1 -> bf16 hi/lo [k][o]; params
    int po=t&63, k0=t>>6;
    #pragma unroll
    for(int it=0;it<16;++it){
      int k=k0+it*8;
      float2 v=*(const float2*)(w1g+(size_t)b*16384+k*128+2*po);
      uint32_t lo, hi=bfpair(v.x,v.y,lo);
      *(uint32_t*)(w1h+k*SQ+po*4)=hi; *(uint32_t*)(w1l+k*SQ+po*4)=lo;
    }
    if(t<256) w0s[t]=w0g[b*256+t];
    else if(t<384) b0s[t-256]=b0g[b*128+(t-256)];
    else b1s[t-384]=b1g[b*128+(t-384)];
    if(t<128){
      w2s[t*4+0]=w2g[b*384+t*3+0]; w2s[t*4+1]=w2g[b*384+t*3+1]; w2s[t*4+2]=w2g[b*384+t*3+2];
    }
    if(t<3) b2s[t]=b2g[b*3+t];
  }
  __syncthreads();

  float c1[8][4], c2[8][4];
  #pragma unroll
  for(int i=0;i<8;++i){ c1[i][0]=c1[i][1]=c1[i][2]=c1[i][3]=0.f; c2[i][0]=c2[i][1]=c2[i][2]=c2[i][3]=0.f; }
  float z3acc=0.f;
  const int d0w=(wid&3)*32, pB=(wid>>2)*32;   // C/D: 32d x 32p per warp
  const int oB=(wid&7)*16, nC=(wid>>3)*32;    // B:   16o x 32n per warp
  const float* pw1src=pwg+(size_t)1*Nn*Pp;
  const float* pw2src=pwg+(size_t)2*Nn*Pp;
  const float* pw3src=pwg+(size_t)3*Nn*Pp;

  conv_q(pw1src, q1h,q1l, 0);
  h1_compute(0);
  __syncthreads();

  for(int tile=0; tile<NTILES; ++tile){
    const int n0=tile*TILE;

    // ===== region 1: conv q2(t); B(t); C(t); F(t-1) =====
    conv_q(pw2src, q2h,q2l, n0);
    {
      float c[4][4];
      #pragma unroll
      for(int i=0;i<4;++i){ c[i][0]=c[i][1]=c[i][2]=c[i][3]=0.f; }
      gemm3_t<8,4>(c, W1H,W1L, H1H,H1L, lane, oB, nC, SQ, SH);
      int o0=oB+(lane>>2);
      float bia0=b1s[o0], bia1=b1s[o0+8];
      #pragma unroll
      for(int bb=0;bb<4;++bb){
        int n=nC+(bb>>1)*16+(bb&1)*8+2*(lane&3);
        float s0=__sinf(W0F*(c[bb][0]+bia0)), s1=__sinf(W0F*(c[bb][1]+bia0));
        float s2=__sinf(W0F*(c[bb][2]+bia1)), s3=__sinf(W0F*(c[bb][3]+bia1));
        uint32_t lo0, hi0=bfpair(s0,s1,lo0);
        uint32_t lo1, hi1=bfpair(s2,s3,lo1);
        *(uint32_t*)(h2h+o0*SH+n*2)=hi0;     *(uint32_t*)(h2l+o0*SH+n*2)=lo0;
        *(uint32_t*)(h2h+(o0+8)*SH+n*2)=hi1; *(uint32_t*)(h2l+(o0+8)*SH+n*2)=lo1;
      }
    }
    gemm3_nt32<4>(c1, H1H,H1L, Q1H,Q1L, lane, d0w, pB, SH, SQ);
    if(tile>0 && t<384){
      int j=t>>7, p=t&127;
      const float* pw3=pw3src+(size_t)(n0-TILE)*Pp+p;
      float ta=0.f, tb=0.f;
      #pragma unroll 8
      for(int n=0;n<TILE;n+=2){
        ta=fmaf(h3s[n*4+j],     pw3[n*Pp],     ta);
        tb=fmaf(h3s[(n+1)*4+j], pw3[(n+1)*Pp], tb);
      }
      z3acc+=ta+tb;
    }
    __syncthreads();

    // ===== region 2: E(t); D(t); conv q1(t+1); h1(t+1) =====
    if(t>=320){
      int u=t-320, n=u/3, j=u-n*3;
      float acc=b2s[j];
      #pragma unroll 8
      for(int o=0;o<128;++o){
        float hv=__bfloat162float(*(__nv_bfloat16*)(h2h+o*SH+n*2));
        float lv=__bfloat162float(*(__nv_bfloat16*)(h2l+o*SH+n*2));
        acc=fmaf(hv+lv, w2s[o*4+j], acc);
      }
      h3s[n*4+j]=acc;
    }
    gemm3_nt32<4>(c2, H2H,H2L, Q2H,Q2L, lane, d0w, pB, SH, SQ);
    if(tile+1<NTILES){
      conv_q(pw1src, q1h,q1l, n0+TILE);
      h1_compute(n0+TILE);
    }
    __syncthreads();
  }

  // final F(63)
  if(t<384){
    int j=t>>7, p=t&127;
    const float* pw3=pw3src+(size_t)(NTILES-1)*TILE*Pp+p;
    float ta=0.f, tb=0.f;
    #pragma unroll 8
    for(int n=0;n<TILE;n+=2){
      ta=fmaf(h3s[n*4+j],     pw3[n*Pp],     ta);
      tb=fmaf(h3s[(n+1)*4+j], pw3[(n+1)*Pp], tb);
    }
    z3acc+=ta+tb;
  }

  // ===== epilogue =====
  __syncthreads();
  float* zs=(float*)(smc+BY_H1H);
  {
    const float* pb1=pbg+128;
    #pragma unroll
    for(int mb=0;mb<2;++mb)
      #pragma unroll
      for(int nb=0;nb<4;++nb){
        int rb2=d0w+mb*16+(lane>>2);
        int col=pB+nb*8+2*(lane&3);
        float* q=&c1[mb*4+nb][0];
        zs[rb2*128+col]      =q[0]+pb1[col];
        zs[rb2*128+col+1]    =q[1]+pb1[col+1];
        zs[(rb2+8)*128+col]  =q[2]+pb1[col];
        zs[(rb2+8)*128+col+1]=q[3]+pb1[col+1];
      }
  }
  __syncthreads();
  {
    const float* g=lngg+128; const float* bb=lnbg+128;
    #pragma unroll
    for(int r=0;r<8;++r){
      int row=wid*8+r;
      float4 v=*(const float4*)(zs+row*128+lane*4);
      ln_row_write(v,g,bb,outg+((size_t)b*ROWS+2+row)*Pp,lane);
    }
  }
  __syncthreads();
  {
    const float* pb2=pbg+256;
    #pragma unroll
    for(int mb=0;mb<2;++mb)
      #pragma unroll
      for(int nb=0;nb<4;++nb){
        int rb2=d0w+mb*16+(lane>>2);
        int col=pB+nb*8+2*(lane&3);
        float* q=&c2[mb*4+nb][0];
        zs[rb2*128+col]      =q[0]+pb2[col];
        zs[rb2*128+col+1]    =q[1]+pb2[col+1];
        zs[(rb2+8)*128+col]  =q[2]+pb2[col];
        zs[(rb2+8)*128+col+1]=q[3]+pb2[col+1];
      }
  }
  __syncthreads();
  {
    const float* g=lngg+256; const float* bb=lnbg+256;
    #pragma unroll
    for(int r=0;r<8;++r){
      int row=wid*8+r;
      float4 v=*(const float4*)(zs+row*128+lane*4);
      ln_row_write(v,g,bb,outg+((size_t)b*ROWS+130+row)*Pp,lane);
    }
  }
  if(t<384){
    int j=t>>7, p=t&127;
    z5s[j*Pp+p]=z3acc+pbg[3*128+p];
  }
  __syncthreads();
  if(wid<3){
    int row=wid;
    float4 v=*(const float4*)(z5s+row*Pp+lane*4);
    ln_row_write(v, lngg+3*128, lnbg+3*128,
                 outg+((size_t)b*ROWS+258+row)*Pp, lane);
  }
}

extern "C" void kernel_launch(void* const* d_in, const int* in_sizes, int n_in,
                              void* d_out, int out_size){
  (void)in_sizes;(void)n_in;(void)out_size;
  const float* xg =(const float*)d_in[6];
  const float* pwg=(const float*)d_in[7];
  const float* pbg=(const float*)d_in[8];
  const float* lngg=(const float*)d_in[9];
  const float* lnbg=(const float*)d_in[10];
  float* outg=(float*)d_out;
  z0_part<<<128,256>>>(xg, pwg);
  cudaFuncSetAttribute(gpf_kernel, cudaFuncAttributeMaxDynamicSharedMemorySize, gpf::SMEM_BYTES);
  gpf_kernel<<<gpf::Bn, gpf::NT, gpf::SMEM_BYTES>>>(
    (const float*)d_in[0],(const float*)d_in[1],(const float*)d_in[2],(const float*)d_in[3],
    (const float*)d_in[4],(const float*)d_in[5],xg,pwg,pbg,lngg,lnbg,outg);
  z0_fin<<<1,256>>>(pbg, lngg, lnbg, outg);
}

// round 17
// speedup vs baseline: 1.4940x; 1.0129x over previous
#include <cuda_runtime.h>
#include <cuda_bf16.h>
#include <cstdint>

namespace gpf {
constexpr int Bn=128, Nn=4096, Pp=128, ROWS=261, TILE=64, NTILES=64, NT=512;
constexpr float W0F=30.f, EPS=1e-5f;
constexpr int SQ=272, SH=144;
constexpr int BY_W1H=0, BY_W1L=34816;
constexpr int BY_H1H=69632, BY_H1L=BY_H1H+18432, BY_H2H=BY_H1L+18432, BY_H2L=BY_H2H+18432;
constexpr int BY_Q1H=143360, BY_Q1L=BY_Q1H+17408, BY_Q2H=BY_Q1L+17408, BY_Q2L=BY_Q2H+17408;
constexpr int BY_W0=212992, BY_B0=BY_W0+1024, BY_B1=BY_B0+512, BY_W2=BY_B1+512,
  BY_B2=BY_W2+2048, BY_H3=BY_B2+32, BY_Z5=BY_H3+2048;   // h3: 2 halves x 256 floats
constexpr int SMEM_BYTES=BY_Z5+1536;  // 220704
}

#define LDSM4T(d,a) asm volatile( \
  "ldmatrix.sync.aligned.m8n8.x4.trans.shared.b16 {%0,%1,%2,%3},[%4];" \
  :"=r"((d)[0]),"=r"((d)[1]),"=r"((d)[2]),"=r"((d)[3]):"r"(a))
#define LDSM4(d,a) asm volatile( \
  "ldmatrix.sync.aligned.m8n8.x4.shared.b16 {%0,%1,%2,%3},[%4];" \
  :"=r"((d)[0]),"=r"((d)[1]),"=r"((d)[2]),"=r"((d)[3]):"r"(a))
#define MMAB(c,a,b0,b1) asm volatile( \
  "mma.sync.aligned.m16n8k16.row.col.f32.bf16.bf16.f32 " \
  "{%0,%1,%2,%3},{%4,%5,%6,%7},{%8,%9},{%0,%1,%2,%3};" \
  :"+f"((c)[0]),"+f"((c)[1]),"+f"((c)[2]),"+f"((c)[3]) \
  :"r"((a)[0]),"r"((a)[1]),"r"((a)[2]),"r"((a)[3]),"r"(b0),"r"(b1))

__device__ __forceinline__ uint32_t smem_u32(const void* p){
  uint32_t a; asm("{ .reg .u64 t; cvta.to.shared.u64 t, %1; cvt.u32.u64 %0, t; }":"=r"(a):"l"(p)); return a;
}
__device__ __forceinline__ uint32_t bfpair(float a, float b, uint32_t& lo){
  __nv_bfloat16 ha=__float2bfloat16(a), hb=__float2bfloat16(b);
  __nv_bfloat162 l; l.x=__float2bfloat16(a-__bfloat162float(ha)); l.y=__float2bfloat16(b-__bfloat162float(hb));
  lo=*(uint32_t*)&l;
  __nv_bfloat162 h; h.x=ha; h.y=hb; return *(uint32_t*)&h;
}
__device__ __forceinline__ void ln_row_write(float4 v, const float* g, const float* bb,
                                             float* orow, int lane){
  float s=(v.x+v.y)+(v.z+v.w);
  #pragma unroll
  for(int o=16;o>0;o>>=1) s+=__shfl_xor_sync(0xffffffffu,s,o);
  float m=s*(1.f/128.f);
  float cx=v.x-m, cy=v.y-m, cz=v.z-m, cw=v.w-m;
  float q=(cx*cx+cy*cy)+(cz*cz+cw*cw);
  #pragma unroll
  for(int o=16;o>0;o>>=1) q+=__shfl_xor_sync(0xffffffffu,q,o);
  float inv=rsqrtf(q*(1.f/128.f)+gpf::EPS);
  float4 gv=*(const float4*)(g+lane*4), bv=*(const float4*)(bb+lane*4);
  float4 ov={cx*inv*gv.x+bv.x, cy*inv*gv.y+bv.y, cz*inv*gv.z+bv.z, cw*inv*gv.w+bv.w};
  *(float4*)(orow+lane*4)=ov;
}

// 3-pass bf16 MMA. A TRANS [k][m]; B TRANS [k][j]. (Phase B)
template<int KS, int NB8>
__device__ __forceinline__ void gemm3_t(float (*c)[4], uint32_t AH, uint32_t AL,
    uint32_t BH, uint32_t BL, int lane, int m0, int j0, int SA, int SB){
  const int r=lane&7, g=lane>>3;
  const uint32_t ao=(uint32_t)(((g&2)*4+r)*SA + (m0+(g&1)*8)*2);
  const uint32_t bo=(uint32_t)(((g&1)*8+r)*SB + (g>>1)*16 + j0*2);
  #pragma unroll
  for(int kk=0;kk<KS;++kk){
    uint32_t ah[4], al[4];
    LDSM4T(ah, AH+kk*16*SA+ao); LDSM4T(al, AL+kk*16*SA+ao);
    #pragma unroll
    for(int b2=0;b2<NB8/2;++b2){
      uint32_t bh[4], bl[4], cb=(uint32_t)(kk*16*SB)+bo+b2*32;
      LDSM4T(bh, BH+cb); LDSM4T(bl, BL+cb);
      MMAB(c[2*b2],ah,bh[0],bh[1]); MMAB(c[2*b2],ah,bl[0],bl[1]); MMAB(c[2*b2],al,bh[0],bh[1]);
      MMAB(c[2*b2+1],ah,bh[2],bh[3]); MMAB(c[2*b2+1],ah,bl[2],bl[3]); MMAB(c[2*b2+1],al,bh[2],bh[3]);
    }
  }
}
// 3-pass bf16 MMA, m32 x n32 warp tile. A NON-TRANS [m][k]; B TRANS [k][j].
template<int KS>
__device__ __forceinline__ void gemm3_nt32(float (*c)[4], uint32_t AH, uint32_t AL,
    uint32_t BH, uint32_t BL, int lane, int m0, int j0, int SA, int SB){
  const int r=lane&7, g=lane>>3;
  const uint32_t ao0=(uint32_t)((m0+(g&1)*8+r)*SA + (g&2)*8);
  const uint32_t ao1=ao0+(uint32_t)(16*SA);
  const uint32_t bo=(uint32_t)(((g&1)*8+r)*SB + (g>>1)*16 + j0*2);
  #pragma unroll
  for(int kk=0;kk<KS;++kk){
    const uint32_t ka=(uint32_t)(kk*32), kb=(uint32_t)(kk*16*SB);
    uint32_t ah0[4], ah1[4], bh0[4], bh1[4];
    LDSM4(ah0, AH+ka+ao0); LDSM4(ah1, AH+ka+ao1);
    LDSM4T(bh0, BH+kb+bo); LDSM4T(bh1, BH+kb+bo+32);
    MMAB(c[0],ah0,bh0[0],bh0[1]); MMAB(c[1],ah0,bh0[2],bh0[3]);
    MMAB(c[2],ah0,bh1[0],bh1[1]); MMAB(c[3],ah0,bh1[2],bh1[3]);
    MMAB(c[4],ah1,bh0[0],bh0[1]); MMAB(c[5],ah1,bh0[2],bh0[3]);
    MMAB(c[6],ah1,bh1[0],bh1[1]); MMAB(c[7],ah1,bh1[2],bh1[3]);
    uint32_t bl0[4], bl1[4];
    LDSM4T(bl0, BL+kb+bo); LDSM4T(bl1, BL+kb+bo+32);
    MMAB(c[0],ah0,bl0[0],bl0[1]); MMAB(c[1],ah0,bl0[2],bl0[3]);
    MMAB(c[2],ah0,bl1[0],bl1[1]); MMAB(c[3],ah0,bl1[2],bl1[3]);
    MMAB(c[4],ah1,bl0[0],bl0[1]); MMAB(c[5],ah1,bl0[2],bl0[3]);
    MMAB(c[6],ah1,bl1[0],bl1[1]); MMAB(c[7],ah1,bl1[2],bl1[3]);
    uint32_t al0[4], al1[4];
    LDSM4(al0, AL+ka+ao0); LDSM4(al1, AL+ka+ao1);
    MMAB(c[0],al0,bh0[0],bh0[1]); MMAB(c[1],al0,bh0[2],bh0[3]);
    MMAB(c[2],al0,bh1[0],bh1[1]); MMAB(c[3],al0,bh1[2],bh1[3]);
    MMAB(c[4],al1,bh0[0],bh0[1]); MMAB(c[5],al1,bh0[2],bh0[3]);
    MMAB(c[6],al1,bh1[0],bh1[1]); MMAB(c[7],al1,bh1[2],bh1[3]);
  }
}

// ---- z0 partials written by main-kernel prologue; reduced+LN'd by z0_fin ----
__device__ float g_z0s[128*256];
__global__ void z0_fin(const float* __restrict__ pbg, const float* __restrict__ lngg,
                       const float* __restrict__ lnbg, float* __restrict__ outg){
  __shared__ float z[2][128];
  int t=threadIdx.x, d=t>>7, p=t&127, lane=t&31, wid=t>>5;
  float acc=0.f;
  #pragma unroll 8
  for(int k=0;k<128;++k) acc+=g_z0s[k*256+t];
  z[d][p]=acc+pbg[p];
  __syncthreads();
  if(wid<2){
    float4 v=*(const float4*)(&z[wid][lane*4]);
    float s=(v.x+v.y)+(v.z+v.w);
    #pragma unroll
    for(int o=16;o>0;o>>=1) s+=__shfl_xor_sync(0xffffffffu,s,o);
    float m=s*(1.f/128.f);
    float cx=v.x-m, cy=v.y-m, cz=v.z-m, cw=v.w-m;
    float q=(cx*cx+cy*cy)+(cz*cz+cw*cw);
    #pragma unroll
    for(int o=16;o>0;o>>=1) q+=__shfl_xor_sync(0xffffffffu,q,o);
    float inv=rsqrtf(q*(1.f/128.f)+gpf::EPS);
    float4 gv=*(const float4*)(lngg+lane*4), bv=*(const float4*)(lnbg+lane*4);
    float4 ov={cx*inv*gv.x+bv.x, cy*inv*gv.y+bv.y, cz*inv*gv.z+bv.z, cw*inv*gv.w+bv.w};
    *(float4*)(&z[wid][lane*4])=ov;
  }
  __syncthreads();
  float4 v0=*(const float4*)(&z[0][lane*4]);
  float4 v1=*(const float4*)(&z[1][lane*4]);
  for(int b=wid; b<gpf::Bn; b+=8){
    *(float4*)(outg+((size_t)b*gpf::ROWS+0)*gpf::Pp+lane*4)=v0;
    *(float4*)(outg+((size_t)b*gpf::ROWS+1)*gpf::Pp+lane*4)=v1;
  }
}

__global__ __launch_bounds__(gpf::NT,1)
void gpf_kernel(const float* __restrict__ w0g, const float* __restrict__ w1g,
                const float* __restrict__ w2g, const float* __restrict__ b0g,
                const float* __restrict__ b1g, const float* __restrict__ b2g,
                const float* __restrict__ xg,  const float* __restrict__ pwg,
                const float* __restrict__ pbg, const float* __restrict__ lngg,
                const float* __restrict__ lnbg, float* __restrict__ outg){
  using namespace gpf;
  extern __shared__ char smc[];
  const int b=blockIdx.x, t=threadIdx.x, lane=t&31, wid=t>>5;
  char *w1h=smc+BY_W1H, *w1l=smc+BY_W1L;
  char *h1h=smc+BY_H1H, *h1l=smc+BY_H1L, *h2h=smc+BY_H2H, *h2l=smc+BY_H2L;
  char *q1h=smc+BY_Q1H, *q1l=smc+BY_Q1L, *q2h=smc+BY_Q2H, *q2l=smc+BY_Q2L;
  float* w0s=(float*)(smc+BY_W0); float* b0s=(float*)(smc+BY_B0); float* b1s=(float*)(smc+BY_B1);
  float* w2s=(float*)(smc+BY_W2); float* b2s=(float*)(smc+BY_B2);
  float* h3s=(float*)(smc+BY_H3); float* z5s=(float*)(smc+BY_Z5);
  const uint32_t W1H=smem_u32(w1h), W1L=smem_u32(w1l);
  const uint32_t H1H=smem_u32(h1h), H1L=smem_u32(h1l), H2H=smem_u32(h2h), H2L=smem_u32(h2l);
  const uint32_t Q1H=smem_u32(q1h), Q1L=smem_u32(q1l), Q2H=smem_u32(q2h), Q2L=smem_u32(q2l);
  const int p2=t&63, nq0=t>>6;

  auto conv_q=[&](const float* src, char* dh, char* dl, int n0){
    #pragma unroll
    for(int it=0;it<8;++it){
      int n2=nq0+it*8;
      float2 v=*(const float2*)(src+(size_t)(n0+n2)*Pp+2*p2);
      uint32_t lo, hi=bfpair(v.x,v.y,lo);
      *(uint32_t*)(dh+n2*SQ+p2*4)=hi; *(uint32_t*)(dl+n2*SQ+p2*4)=lo;
    }
  };
  auto h1_compute=[&](int n0){
    float4 xv=*(const float4*)(xg+(size_t)n0*2+lane*4);
    #pragma unroll
    for(int it=0;it<8;++it){
      int d=wid+it*16;
      float wa=w0s[d], wb=w0s[128+d], bi=b0s[d];
      float s0=__sinf(W0F*fmaf(xv.x,wa,fmaf(xv.y,wb,bi)));
      float s1=__sinf(W0F*fmaf(xv.z,wa,fmaf(xv.w,wb,bi)));
      uint32_t lo, hi=bfpair(s0,s1,lo);
      *(uint32_t*)(h1h+d*SH+lane*4)=hi; *(uint32_t*)(h1l+d*SH+lane*4)=lo;
    }
  };

  // ---- z0 slice for this CTA (independent; overlaps the smem fills below) ----
  if(t<256){
    int d=t>>7, p=t&127, n0=b*32;
    float acc=0.f;
    #pragma unroll 8
    for(int n=0;n<32;++n)
      acc=fmaf(xg[(n0+n)*2+d], pwg[(size_t)(n0+n)*Pp+p], acc);
    g_z0s[b*256+t]=acc;
  }

  { // one-time: w1 -> bf16 hi/lo [k][o]; params
    int po=t&63, k0=t>>6;
    #pragma unroll
    for(int it=0;it<16;++it){
      int k=k0+it*8;
      float2 v=*(const float2*)(w1g+(size_t)b*16384+k*128+2*po);
      uint32_t lo, hi=bfpair(v.x,v.y,lo);
      *(uint32_t*)(w1h+k*SQ+po*4)=hi; *(uint32_t*)(w1l+k*SQ+po*4)=lo;
    }
    if(t<256) w0s[t]=w0g[b*256+t];
    else if(t<384) b0s[t-256]=b0g[b*128+(t-256)];
    else b1s[t-384]=b1g[b*128+(t-384)];
    if(t<128){
      w2s[t*4+0]=w2g[b*384+t*3+0]; w2s[t*4+1]=w2g[b*384+t*3+1]; w2s[t*4+2]=w2g[b*384+t*3+2];
    }
    if(t<3) b2s[t]=b2g[b*3+t];
  }
  __syncthreads();

  float c1[8][4], c2[8][4];
  #pragma unroll
  for(int i=0;i<8;++i){ c1[i][0]=c1[i][1]=c1[i][2]=c1[i][3]=0.f; c2[i][0]=c2[i][1]=c2[i][2]=c2[i][3]=0.f; }
  float z3acc=0.f;
  const int d0w=(wid&3)*32, pB=(wid>>2)*32;   // C/D: 32d x 32p per warp
  const int oB=(wid&7)*16, nC=(wid>>3)*32;    // B:   16o x 32n per warp
  const float* pw1src=pwg+(size_t)1*Nn*Pp;
  const float* pw2src=pwg+(size_t)2*Nn*Pp;
  const float* pw3src=pwg+(size_t)3*Nn*Pp;

  conv_q(pw1src, q1h,q1l, 0);
  h1_compute(0);
  __syncthreads();

  for(int tile=0; tile<NTILES; ++tile){
    const int n0=tile*TILE;

    // ===== region 1: conv q2(t); B(t); C(t); F(t-1) =====
    conv_q(pw2src, q2h,q2l, n0);
    {
      float c[4][4];
      #pragma unroll
      for(int i=0;i<4;++i){ c[i][0]=c[i][1]=c[i][2]=c[i][3]=0.f; }
      gemm3_t<8,4>(c, W1H,W1L, H1H,H1L, lane, oB, nC, SQ, SH);
      int o0=oB+(lane>>2);
      float bia0=b1s[o0], bia1=b1s[o0+8];
      #pragma unroll
      for(int bb=0;bb<4;++bb){
        int n=nC+(bb>>1)*16+(bb&1)*8+2*(lane&3);
        float s0=__sinf(W0F*(c[bb][0]+bia0)), s1=__sinf(W0F*(c[bb][1]+bia0));
        float s2=__sinf(W0F*(c[bb][2]+bia1)), s3=__sinf(W0F*(c[bb][3]+bia1));
        uint32_t lo0, hi0=bfpair(s0,s1,lo0);
        uint32_t lo1, hi1=bfpair(s2,s3,lo1);
        *(uint32_t*)(h2h+o0*SH+n*2)=hi0;     *(uint32_t*)(h2l+o0*SH+n*2)=lo0;
        *(uint32_t*)(h2h+(o0+8)*SH+n*2)=hi1; *(uint32_t*)(h2l+(o0+8)*SH+n*2)=lo1;
      }
    }
    gemm3_nt32<4>(c1, H1H,H1L, Q1H,Q1L, lane, d0w, pB, SH, SQ);
    if(tile>0 && t<384){
      int j=t>>7, p=t&127;
      const float* pw3=pw3src+(size_t)(n0-TILE)*Pp+p;
      float ta=0.f, tb=0.f;
      #pragma unroll 8
      for(int n=0;n<TILE;n+=2){
        float h3a=h3s[n*4+j]      + h3s[256+n*4+j];
        float h3b=h3s[(n+1)*4+j]  + h3s[256+(n+1)*4+j];
        ta=fmaf(h3a, pw3[n*Pp],     ta);
        tb=fmaf(h3b, pw3[(n+1)*Pp], tb);
      }
      z3acc+=ta+tb;
    }
    __syncthreads();

    // ===== region 2: E(t) on warps 4-15 (2-way o-split); D(t); conv q1(t+1); h1(t+1) =====
    if(t>=128){
      int u=t-128, half=u>=192, v=u-half*192, n=v/3, j=v-n*3;
      float acc = half? 0.f : b2s[j];
      const char* ph=h2h+(half*64)*SH+n*2;
      const char* pl=h2l+(half*64)*SH+n*2;
      const float* wj=w2s+(half*64)*4+j;
      #pragma unroll 8
      for(int o=0;o<64;++o){
        float hv=__bfloat162float(*(const __nv_bfloat16*)(ph+o*SH));
        float lv=__bfloat162float(*(const __nv_bfloat16*)(pl+o*SH));
        acc=fmaf(hv+lv, wj[o*4], acc);
      }
      h3s[half*256+n*4+j]=acc;
    }
    gemm3_nt32<4>(c2, H2H,H2L, Q2H,Q2L, lane, d0w, pB, SH, SQ);
    if(tile+1<NTILES){
      conv_q(pw1src, q1h,q1l, n0+TILE);
      h1_compute(n0+TILE);
    }
    __syncthreads();
  }

  // final F(63)
  if(t<384){
    int j=t>>7, p=t&127;
    const float* pw3=pw3src+(size_t)(NTILES-1)*TILE*Pp+p;
    float ta=0.f, tb=0.f;
    #pragma unroll 8
    for(int n=0;n<TILE;n+=2){
      float h3a=h3s[n*4+j]      + h3s[256+n*4+j];
      float h3b=h3s[(n+1)*4+j]  + h3s[256+(n+1)*4+j];
      ta=fmaf(h3a, pw3[n*Pp],     ta);
      tb=fmaf(h3b, pw3[(n+1)*Pp], tb);
    }
    z3acc+=ta+tb;
  }

  // ===== epilogue =====
  __syncthreads();
  float* zs=(float*)(smc+BY_H1H);
  {
    const float* pb1=pbg+128;
    #pragma unroll
    for(int mb=0;mb<2;++mb)
      #pragma unroll
      for(int nb=0;nb<4;++nb){
        int rb2=d0w+mb*16+(lane>>2);
        int col=pB+nb*8+2*(lane&3);
        float* q=&c1[mb*4+nb][0];
        zs[rb2*128+col]      =q[0]+pb1[col];
        zs[rb2*128+col+1]    =q[1]+pb1[col+1];
        zs[(rb2+8)*128+col]  =q[2]+pb1[col];
        zs[(rb2+8)*128+col+1]=q[3]+pb1[col+1];
      }
  }
  __syncthreads();
  {
    const float* g=lngg+128; const float* bb=lnbg+128;
    #pragma unroll
    for(int r=0;r<8;++r){
      int row=wid*8+r;
      float4 v=*(const float4*)(zs+row*128+lane*4);
      ln_row_write(v,g,bb,outg+((size_t)b*ROWS+2+row)*Pp,lane);
    }
  }
  __syncthreads();
  {
    const float* pb2=pbg+256;
    #pragma unroll
    for(int mb=0;mb<2;++mb)
      #pragma unroll
      for(int nb=0;nb<4;++nb){
        int rb2=d0w+mb*16+(lane>>2);
        int col=pB+nb*8+2*(lane&3);
        float* q=&c2[mb*4+nb][0];
        zs[rb2*128+col]      =q[0]+pb2[col];
        zs[rb2*128+col+1]    =q[1]+pb2[col+1];
        zs[(rb2+8)*128+col]  =q[2]+pb2[col];
        zs[(rb2+8)*128+col+1]=q[3]+pb2[col+1];
      }
  }
  __syncthreads();
  {
    const float* g=lngg+256; const float* bb=lnbg+256;
    #pragma unroll
    for(int r=0;r<8;++r){
      int row=wid*8+r;
      float4 v=*(const float4*)(zs+row*128+lane*4);
      ln_row_write(v,g,bb,outg+((size_t)b*ROWS+130+row)*Pp,lane);
    }
  }
  if(t<384){
    int j=t>>7, p=t&127;
    z5s[j*Pp+p]=z3acc+pbg[3*128+p];
  }
  __syncthreads();
  if(wid<3){
    int row=wid;
    float4 v=*(const float4*)(z5s+row*Pp+lane*4);
    ln_row_write(v, lngg+3*128, lnbg+3*128,
                 outg+((size_t)b*ROWS+258+row)*Pp, lane);
  }
}

extern "C" void kernel_launch(void* const* d_in, const int* in_sizes, int n_in,
                              void* d_out, int out_size){
  (void)in_sizes;(void)n_in;(void)out_size;
  const float* xg =(const float*)d_in[6];
  const float* pwg=(const float*)d_in[7];
  const float* pbg=(const float*)d_in[8];
  const float* lngg=(const float*)d_in[9];
  const float* lnbg=(const float*)d_in[10];
  float* outg=(float*)d_out;
  cudaFuncSetAttribute(gpf_kernel, cudaFuncAttributeMaxDynamicSharedMemorySize, gpf::SMEM_BYTES);
  gpf_kernel<<<gpf::Bn, gpf::NT, gpf::SMEM_BYTES>>>(
    (const float*)d_in[0],(const float*)d_in[1],(const float*)d_in[2],(const float*)d_in[3],
    (const float*)d_in[4],(const float*)d_in[5],xg,pwg,pbg,lngg,lnbg,outg);
  z0_fin<<<1,256>>>(pbg, lngg, lnbg, outg);
}